// round 12
// baseline (speedup 1.0000x reference)
#include <cuda_runtime.h>
#include <cuda_bf16.h>
#include <math.h>
#include <stdint.h>

#define T_TYPES 11
#define NUM_TX  131072
#define N_ENT   131072
#define NE      262144
#define H       128
#define TXF     394
#define LN_EPS  1e-5f
#define INV_SQRT_D 0.08838834764831845f   // 1/sqrt(128)

// bf16 tile strides (bytes): 128 bf16 = 256B + 16B pad -> conflict-free ldmatrix
#define SA 272
#define ATILE2  69632     // 256 rows * 272B
#define BTILE   34816     // 128 n-rows * 272B
#define W2T     17408     // 64 n-rows * 272B
#define ZXW     192       // u32 words per g_zx row: [zb 64][x 128]

// ---------------- scratch (device globals; no cudaMalloc allowed) ----------
__device__ uint32_t g_zx [T_TYPES][(size_t)N_ENT * ZXW]; // [zb bf16x2 | x fp32]
__device__ float g_xagg[T_TYPES][(size_t)N_ENT * H];
__device__ float g_hw  [T_TYPES][(size_t)N_ENT * H];
__device__ float g_c   [T_TYPES][N_ENT];
__device__ float g_h1  [(size_t)NUM_TX * H];
__device__ float g_weff[H * H];               // Wz[k][n]
__device__ float g_wkbq[H];

// precomputed split-bf16 swizzled B images: [hi BTILE][lo BTILE]
__device__ uint4 g_img_v [(2 * BTILE) / 16];
__device__ uint4 g_img_s [(2 * BTILE) / 16];
__device__ uint4 g_img_w1[T_TYPES][(2 * BTILE) / 16];

// CSR over dst, per type
__device__ int g_deg [T_TYPES][N_ENT];
__device__ int g_ptr [T_TYPES][N_ENT];
__device__ int g_cur [T_TYPES][N_ENT];
__device__ int g_col [T_TYPES][NE];

// ================= helpers ===================================================
__device__ __forceinline__ uint32_t smem_u32(const void* p) {
    uint32_t a;
    asm("{ .reg .u64 t; cvta.to.shared.u64 t, %1; cvt.u32.u64 %0, t; }" : "=r"(a) : "l"(p));
    return a;
}
__device__ __forceinline__ void ldmx4(uint32_t* r, uint32_t addr) {
    asm volatile("ldmatrix.sync.aligned.m8n8.x4.shared.b16 {%0,%1,%2,%3}, [%4];"
        : "=r"(r[0]), "=r"(r[1]), "=r"(r[2]), "=r"(r[3]) : "r"(addr));
}
__device__ __forceinline__ void mma_bf16(float* c, const uint32_t* a, uint32_t b0, uint32_t b1) {
    asm volatile("mma.sync.aligned.m16n8k16.row.col.f32.bf16.bf16.f32 "
        "{%0,%1,%2,%3}, {%4,%5,%6,%7}, {%8,%9}, {%0,%1,%2,%3};"
        : "+f"(c[0]), "+f"(c[1]), "+f"(c[2]), "+f"(c[3])
        : "r"(a[0]), "r"(a[1]), "r"(a[2]), "r"(a[3]), "r"(b0), "r"(b1));
}
__device__ __forceinline__ uint32_t bfpack(float a, float b) {
    __nv_bfloat162 t = __floats2bfloat162_rn(a, b);
    return reinterpret_cast<uint32_t&>(t);
}
__device__ __forceinline__ void split4(float4 v, uint32_t* hi, uint32_t* lo) {
    __nv_bfloat16 hx = __float2bfloat16(v.x), hy = __float2bfloat16(v.y);
    __nv_bfloat16 hz = __float2bfloat16(v.z), hw = __float2bfloat16(v.w);
    __nv_bfloat162 h01; h01.x = hx; h01.y = hy;
    __nv_bfloat162 h23; h23.x = hz; h23.y = hw;
    hi[0] = reinterpret_cast<uint32_t&>(h01);
    hi[1] = reinterpret_cast<uint32_t&>(h23);
    lo[0] = bfpack(v.x - __bfloat162float(hx), v.y - __bfloat162float(hy));
    lo[1] = bfpack(v.z - __bfloat162float(hz), v.w - __bfloat162float(hw));
}
__device__ __forceinline__ void split2(float a, float b, uint32_t& hi, uint32_t& lo) {
    __nv_bfloat16 ha = __float2bfloat16(a), hb = __float2bfloat16(b);
    __nv_bfloat162 hp; hp.x = ha; hp.y = hb;
    hi = reinterpret_cast<uint32_t&>(hp);
    lo = bfpack(a - __bfloat162float(ha), b - __bfloat162float(hb));
}
__device__ __forceinline__ void conv_B(const float* __restrict__ W, char* bh, char* bl,
                                       int tid, int nthr) {
    for (int i = tid; i < H * H; i += nthr) {
        const int k = i >> 7, n = i & 127;
        const float w = W[i];
        const __nv_bfloat16 h = __float2bfloat16(w);
        *(__nv_bfloat16*)(bh + n * SA + k * 2) = h;
        *(__nv_bfloat16*)(bl + n * SA + k * 2) = __float2bfloat16(w - __bfloat162float(h));
    }
}
__device__ __forceinline__ void copy_img(const uint4* __restrict__ img, char* bh, int tid) {
    uint4* d = (uint4*)bh;
    for (int i = tid; i < (2 * BTILE) / 16; i += 512) d[i] = __ldg(img + i);
}

// ================= prep: Wz = Wk Wq^T, wkbq = Wk bq ==========================
__global__ void k_prep(const float* __restrict__ Wq, const float* __restrict__ Wk,
                       const float* __restrict__ bq) {
    __shared__ float wkrow[H];
    const int b = blockIdx.x, a = threadIdx.x;
    wkrow[a] = Wk[b * H + a];
    __syncthreads();
    float s = 0.0f;
    #pragma unroll 4
    for (int j = 0; j < H; j++) s = fmaf(wkrow[j], Wq[a * H + j], s);
    g_weff[b * H + a] = s;
    if (b == 0) {
        float t = 0.0f;
        for (int j = 0; j < H; j++) t = fmaf(Wk[a * H + j], bq[j], t);
        g_wkbq[a] = t;
    }
}

// ================= build split-bf16 B images =================================
__global__ void k_mkimg(const float* __restrict__ Wv, const float* __restrict__ Ws,
                        const float* __restrict__ W1) {
    const int b = blockIdx.x;
    const float* W;
    uint8_t* img;
    if (b == 0)      { W = Wv; img = (uint8_t*)g_img_v; }
    else if (b == 1) { W = Ws; img = (uint8_t*)g_img_s; }
    else             { W = W1 + (size_t)(TXF + (b - 2) * H) * H;
                       img = (uint8_t*)g_img_w1[b - 2]; }
    for (int i = threadIdx.x; i < H * H; i += 256) {
        const int k = i >> 7, n = i & 127;
        const float w = W[i];
        const __nv_bfloat16 h = __float2bfloat16(w);
        *(__nv_bfloat16*)(img + n * SA + k * 2) = h;
        *(__nv_bfloat16*)(img + BTILE + n * SA + k * 2) =
            __float2bfloat16(w - __bfloat162float(h));
    }
}

// ================= CSR build =================================================
__global__ void k_zero_deg() {
    const int i = blockIdx.x * blockDim.x + threadIdx.x;
    if (i < T_TYPES * N_ENT) ((int*)g_deg)[i] = 0;
}
__global__ void k_count(const int* __restrict__ edst) {
    const int i = blockIdx.x * blockDim.x + threadIdx.x;
    if (i >= T_TYPES * NE) return;
    const int t = i / NE;
    atomicAdd(&g_deg[t][edst[i]], 1);
}
// one block per type: 1024 threads, each scans 128 contiguous entries
__global__ void __launch_bounds__(1024) k_scan() {
    const int t = blockIdx.x, tid = threadIdx.x;
    const int base = tid * 128;
    int s = 0;
    for (int j = 0; j < 128; j++) s += g_deg[t][base + j];
    __shared__ int sm[1024];
    sm[tid] = s; __syncthreads();
    for (int off = 1; off < 1024; off <<= 1) {
        int x = (tid >= off) ? sm[tid - off] : 0;
        __syncthreads();
        sm[tid] += x;
        __syncthreads();
    }
    int run = (tid == 0) ? 0 : sm[tid - 1];
    for (int j = 0; j < 128; j++) {
        const int i = base + j;
        g_ptr[t][i] = run;
        g_cur[t][i] = run;
        run += g_deg[t][i];
    }
}
__global__ void k_fill(const int* __restrict__ esrc, const int* __restrict__ edst) {
    const int i = blockIdx.x * blockDim.x + threadIdx.x;
    if (i >= T_TYPES * NE) return;
    const int t = i / NE;
    const int slot = atomicAdd(&g_cur[t][edst[i]], 1);
    g_col[t][slot] = esrc[i];
}

// ================= MMA core (256-row tile, acc[2][8][4], 16 warps) ==========
#define MMA_TILE256(AhA, AlA, BhA, BlA, acc, rbw, ch, lane)                          \
    {                                                                                 \
        const uint32_t arow = (rbw) + ((lane) & 15);                                  \
        const uint32_t aqof = ((lane) >> 4) * 16;                                     \
        const uint32_t brow = (ch) * 64 + (((lane) >> 4) * 8) + ((lane) & 7);         \
        const uint32_t bqof = (((lane) >> 3) & 1) * 16;                               \
        _Pragma("unroll")                                                             \
        for (int ks = 0; ks < 8; ks++) {                                              \
            const uint32_t kb = ks * 32;                                              \
            uint32_t ah[2][4], al[2][4], bf[4][4];                                    \
            _Pragma("unroll")                                                         \
            for (int mt = 0; mt < 2; mt++) {                                          \
                const uint32_t ao = (arow + mt * 16) * SA + kb + aqof;                \
                ldmx4(ah[mt], (AhA) + ao);                                            \
                ldmx4(al[mt], (AlA) + ao);                                            \
            }                                                                         \
            _Pragma("unroll")                                                         \
            for (int np = 0; np < 4; np++)                                            \
                ldmx4(bf[np], (BhA) + (brow + np * 16) * SA + kb + bqof);             \
            _Pragma("unroll")                                                         \
            for (int np = 0; np < 4; np++)                                            \
                _Pragma("unroll")                                                     \
                for (int sb = 0; sb < 2; sb++) {                                      \
                    const int nt = np * 2 + sb;                                       \
                    _Pragma("unroll")                                                 \
                    for (int mt = 0; mt < 2; mt++) {                                  \
                        mma_bf16(acc[mt][nt], ah[mt], bf[np][sb*2], bf[np][sb*2+1]);  \
                        mma_bf16(acc[mt][nt], al[mt], bf[np][sb*2], bf[np][sb*2+1]);  \
                    }                                                                 \
                }                                                                     \
            _Pragma("unroll")                                                         \
            for (int np = 0; np < 4; np++)                                            \
                ldmx4(bf[np], (BlA) + (brow + np * 16) * SA + kb + bqof);             \
            _Pragma("unroll")                                                         \
            for (int np = 0; np < 4; np++)                                            \
                _Pragma("unroll")                                                     \
                for (int sb = 0; sb < 2; sb++) {                                      \
                    const int nt = np * 2 + sb;                                       \
                    _Pragma("unroll")                                                 \
                    for (int mt = 0; mt < 2; mt++)                                    \
                        mma_bf16(acc[mt][nt], ah[mt], bf[np][sb*2], bf[np][sb*2+1]);  \
                }                                                                     \
        }                                                                             \
    }

// ================= init_h1 via MMA: b1 + tx_x @ W1[0:394] ====================
__global__ void __launch_bounds__(512, 1) k_init_mma(const float* __restrict__ tx,
                                                     const float* __restrict__ W1,
                                                     const float* __restrict__ b1) {
    extern __shared__ char dsraw[];
    __shared__ float s_b1[H];
    const uint32_t raw  = smem_u32(dsraw);
    const uint32_t base = (raw + 1023u) & ~1023u;
    char* dsm = dsraw + (base - raw);
    const int tid = threadIdx.x, warp = tid >> 5, lane = tid & 31;

    char* Ahp = dsm;
    char* Alp = dsm + ATILE2;
    char* Bhp = dsm + 2 * ATILE2;
    char* Blp = Bhp + BTILE;
    const uint32_t AhA = smem_u32(Ahp), AlA = smem_u32(Alp);
    const uint32_t BhA = smem_u32(Bhp), BlA = smem_u32(Blp);

    if (tid < H) s_b1[tid] = b1[tid];

    const int rbw = (warp & 7) * 32;
    const int ch  = warp >> 3;

    for (int tile = blockIdx.x; tile < NUM_TX / 256; tile += gridDim.x) {
        const int rb = tile * 256;
        float acc[2][8][4];
        #pragma unroll
        for (int mt = 0; mt < 2; mt++)
            #pragma unroll
            for (int nt = 0; nt < 8; nt++)
                #pragma unroll
                for (int q = 0; q < 4; q++) acc[mt][nt][q] = 0.0f;

        for (int chunk = 0; chunk < 4; chunk++) {
            __syncthreads();
            const int kcols = (chunk < 3) ? 128 : 16;
            for (int i = tid; i < kcols * H; i += 512) {
                const int k = i >> 7, n = i & 127;
                const int kk = chunk * 128 + k;
                const float w = (kk < TXF) ? W1[(size_t)kk * H + n] : 0.0f;
                const __nv_bfloat16 h = __float2bfloat16(w);
                *(__nv_bfloat16*)(Bhp + n * SA + k * 2) = h;
                *(__nv_bfloat16*)(Blp + n * SA + k * 2) =
                    __float2bfloat16(w - __bfloat162float(h));
            }
            const int r = tid >> 1, hf = tid & 1;
            const float* rowp = tx + (size_t)(rb + r) * TXF;
            if (chunk < 3) {
                const float2* src = (const float2*)(rowp + chunk * 128 + hf * 64);
                char* ah = Ahp + r * SA + hf * 128;
                char* al = Alp + r * SA + hf * 128;
                #pragma unroll
                for (int j = 0; j < 16; j++) {
                    const float2 a = __ldg(src + j * 2);
                    const float2 b = __ldg(src + j * 2 + 1);
                    float4 v = { a.x, a.y, b.x, b.y };
                    uint32_t hi[2], lo[2];
                    split4(v, hi, lo);
                    *(uint32_t*)(ah + j * 8)     = hi[0];
                    *(uint32_t*)(ah + j * 8 + 4) = hi[1];
                    *(uint32_t*)(al + j * 8)     = lo[0];
                    *(uint32_t*)(al + j * 8 + 4) = lo[1];
                }
            } else {
                float vals[8];
                #pragma unroll
                for (int j = 0; j < 8; j++) {
                    const int c = 384 + hf * 8 + j;
                    vals[j] = (c < TXF) ? __ldg(rowp + c) : 0.0f;
                }
                char* ah = Ahp + r * SA + hf * 16;
                char* al = Alp + r * SA + hf * 16;
                #pragma unroll
                for (int p = 0; p < 4; p++) {
                    float4 v = { vals[p*2], vals[p*2+1], 0.0f, 0.0f };
                    uint32_t hi[2], lo[2];
                    split4(v, hi, lo);
                    *(uint32_t*)(ah + p * 4) = hi[0];
                    *(uint32_t*)(al + p * 4) = lo[0];
                }
            }
            __syncthreads();

            const uint32_t arow = rbw + (lane & 15);
            const uint32_t aqof = (lane >> 4) * 16;
            const uint32_t brow = ch * 64 + ((lane >> 4) * 8) + (lane & 7);
            const uint32_t bqof = ((lane >> 3) & 1) * 16;
            const int nks = (chunk < 3) ? 8 : 1;
            for (int ks = 0; ks < nks; ks++) {
                const uint32_t kb = ks * 32;
                uint32_t ah[2][4], al[2][4], bf[4][4];
                #pragma unroll
                for (int mt = 0; mt < 2; mt++) {
                    const uint32_t ao = (arow + mt * 16) * SA + kb + aqof;
                    ldmx4(ah[mt], AhA + ao);
                    ldmx4(al[mt], AlA + ao);
                }
                #pragma unroll
                for (int np = 0; np < 4; np++)
                    ldmx4(bf[np], BhA + (brow + np * 16) * SA + kb + bqof);
                #pragma unroll
                for (int np = 0; np < 4; np++)
                    #pragma unroll
                    for (int sb = 0; sb < 2; sb++) {
                        const int nt = np * 2 + sb;
                        #pragma unroll
                        for (int mt = 0; mt < 2; mt++) {
                            mma_bf16(acc[mt][nt], ah[mt], bf[np][sb*2], bf[np][sb*2+1]);
                            mma_bf16(acc[mt][nt], al[mt], bf[np][sb*2], bf[np][sb*2+1]);
                        }
                    }
                #pragma unroll
                for (int np = 0; np < 4; np++)
                    ldmx4(bf[np], BlA + (brow + np * 16) * SA + kb + bqof);
                #pragma unroll
                for (int np = 0; np < 4; np++)
                    #pragma unroll
                    for (int sb = 0; sb < 2; sb++) {
                        const int nt = np * 2 + sb;
                        #pragma unroll
                        for (int mt = 0; mt < 2; mt++)
                            mma_bf16(acc[mt][nt], ah[mt], bf[np][sb*2], bf[np][sb*2+1]);
                    }
            }
        }
        #pragma unroll
        for (int mt = 0; mt < 2; mt++) {
            const int row0 = rb + rbw + mt * 16 + (lane >> 2);
            #pragma unroll
            for (int nt = 0; nt < 8; nt++) {
                const int col = ch * 64 + nt * 8 + (lane & 3) * 2;
                const float b0 = s_b1[col], b1v = s_b1[col + 1];
                float2 v0 = { acc[mt][nt][0] + b0, acc[mt][nt][1] + b1v };
                float2 v1 = { acc[mt][nt][2] + b0, acc[mt][nt][3] + b1v };
                *(float2*)(g_h1 + (size_t)row0 * H + col)       = v0;
                *(float2*)(g_h1 + (size_t)(row0 + 8) * H + col) = v1;
            }
        }
    }
}

// ====== Z GEMM (ALL types): gather x into zx row, zb = bf16(x@Wz), c =========
__global__ void __launch_bounds__(512, 1) k_z_mma(const float* __restrict__ emb,
                                                  const int* __restrict__ idx) {
    extern __shared__ char dsraw[];
    __shared__ float s_wkbq[H];
    const uint32_t raw  = smem_u32(dsraw);
    const uint32_t base = (raw + 1023u) & ~1023u;
    char* dsm = dsraw + (base - raw);
    const int tid = threadIdx.x, warp = tid >> 5, lane = tid & 31;

    char* Ahp = dsm;
    char* Alp = dsm + ATILE2;
    char* Bhp = dsm + 2 * ATILE2;
    char* Blp = Bhp + BTILE;
    conv_B(g_weff, Bhp, Blp, tid, 512);
    if (tid < H) s_wkbq[tid] = g_wkbq[tid];
    __syncthreads();

    const uint32_t AhA = smem_u32(Ahp), AlA = smem_u32(Alp);
    const uint32_t BhA = smem_u32(Bhp), BlA = smem_u32(Blp);
    const int rbw = (warp & 7) * 32;
    const int ch  = warp >> 3;

    for (int tile = blockIdx.x; tile < T_TYPES * (N_ENT / 256); tile += gridDim.x) {
        const int t  = tile >> 9;                 // 512 tiles per type
        const int rb = (tile & 511) * 256;
        const float* embt = emb + (size_t)t * N_ENT * H;
        const int*   idxt = idx + (size_t)t * N_ENT;
        {
            const int r = tid >> 1, hf = tid & 1;
            const int e = __ldg(idxt + rb + r);
            const float4* src = (const float4*)(embt + (size_t)e * H) + hf * 16;
            float4* xdst = (float4*)(g_zx[t] + (size_t)(rb + r) * ZXW + 64) + hf * 16;
            char* ah = Ahp + r * SA + hf * 128;
            char* al = Alp + r * SA + hf * 128;
            float cp = 0.0f;
            #pragma unroll
            for (int j = 0; j < 16; j++) {
                const float4 v = __ldg(src + j);
                uint32_t hi[2], lo[2];
                split4(v, hi, lo);
                *(uint32_t*)(ah + j * 8)     = hi[0];
                *(uint32_t*)(ah + j * 8 + 4) = hi[1];
                *(uint32_t*)(al + j * 8)     = lo[0];
                *(uint32_t*)(al + j * 8 + 4) = lo[1];
                xdst[j] = v;
                const float* wb = s_wkbq + hf * 64 + j * 4;
                cp += v.x * wb[0] + v.y * wb[1] + v.z * wb[2] + v.w * wb[3];
            }
            cp += __shfl_xor_sync(0xffffffffu, cp, 1);
            if (hf == 0) g_c[t][rb + r] = cp;
        }
        __syncthreads();

        float acc[2][8][4];
        #pragma unroll
        for (int mt = 0; mt < 2; mt++)
            #pragma unroll
            for (int nt = 0; nt < 8; nt++)
                #pragma unroll
                for (int q = 0; q < 4; q++) acc[mt][nt][q] = 0.0f;

        MMA_TILE256(AhA, AlA, BhA, BlA, acc, rbw, ch, lane);

        #pragma unroll
        for (int mt = 0; mt < 2; mt++) {
            const int row0 = rb + rbw + mt * 16 + (lane >> 2);
            #pragma unroll
            for (int nt = 0; nt < 8; nt++) {
                const int col = ch * 64 + nt * 8 + (lane & 3) * 2;
                g_zx[t][(size_t)row0 * ZXW + (col >> 1)] =
                    bfpack(acc[mt][nt][0], acc[mt][nt][1]);
                g_zx[t][(size_t)(row0 + 8) * ZXW + (col >> 1)] =
                    bfpack(acc[mt][nt][2], acc[mt][nt][3]);
            }
        }
        __syncthreads();
    }
}

// ================= attention aggregation (ALL types; warp per dst) ===========
__global__ void __launch_bounds__(256) k_attn() {
    const int warp = threadIdx.x >> 5, lane = threadIdx.x & 31;
    const int t = blockIdx.x >> 14;               // 16384 blocks per type
    const int d = (blockIdx.x & 16383) * 8 + warp;
    const float4 xd4 = ((const float4*)(g_zx[t] + (size_t)d * ZXW + 64))[lane];
    const int start = g_ptr[t][d], deg = g_deg[t][d];

    float den = 0.0f;
    float4 acc = {0.0f, 0.0f, 0.0f, 0.0f};
    for (int e = 0; e < deg; e++) {
        const int s = g_col[t][start + e];
        const uint32_t* rowp = g_zx[t] + (size_t)s * ZXW;
        const uint2 z2 = *((const uint2*)rowp + lane);
        const float2 z0 = __bfloat1622float2(*(const __nv_bfloat162*)&z2.x);
        const float2 z1 = __bfloat1622float2(*(const __nv_bfloat162*)&z2.y);
        const float4 x4 = ((const float4*)(rowp + 64))[lane];
        float dot = xd4.x * z0.x + xd4.y * z0.y + xd4.z * z1.x + xd4.w * z1.y;
        #pragma unroll
        for (int o = 16; o; o >>= 1) dot += __shfl_xor_sync(0xffffffffu, dot, o);
        const float w = expf((dot + __ldg(&g_c[t][s])) * INV_SQRT_D);
        den += w;
        acc.x += w * x4.x; acc.y += w * x4.y; acc.z += w * x4.z; acc.w += w * x4.w;
    }
    const float inv = (deg > 0) ? 1.0f / den : 0.0f;
    float4 o4 = { acc.x * inv, acc.y * inv, acc.z * inv, acc.w * inv };
    ((float4*)(g_xagg[t] + (size_t)d * H))[lane] = o4;
}

// ===== fused (ALL types): h = LN(xagg@Wv + x@Ws + bv+bs)*g+b; hw = h@W1_t ====
__global__ void __launch_bounds__(512, 1) k_fused(
    const float* __restrict__ bv, const float* __restrict__ bs,
    const float* __restrict__ lns, const float* __restrict__ lnb) {
    extern __shared__ char dsraw[];
    __shared__ float s_bias[H], s_g[H], s_b[H];
    __shared__ float sS1[256], sS2[256], sMu[256], sRstd[256];
    const uint32_t raw  = smem_u32(dsraw);
    const uint32_t base = (raw + 1023u) & ~1023u;
    char* dsm = dsraw + (base - raw);
    const int tid = threadIdx.x, warp = tid >> 5, lane = tid & 31;

    char* Ahp = dsm;
    char* Alp = dsm + ATILE2;
    char* Bhp = dsm + 2 * ATILE2;
    const uint32_t AhA = smem_u32(Ahp), AlA = smem_u32(Alp);
    const uint32_t BhA = smem_u32(Bhp), BlA = BhA + BTILE;
    const int rbw = (warp & 7) * 32;
    const int ch  = warp >> 3;

    for (int tile = blockIdx.x; tile < T_TYPES * (N_ENT / 256); tile += gridDim.x) {
        const int t  = tile >> 9;
        const int rb = (tile & 511) * 256;
        float acc[2][8][4];
        #pragma unroll
        for (int mt = 0; mt < 2; mt++)
            #pragma unroll
            for (int nt = 0; nt < 8; nt++)
                #pragma unroll
                for (int q = 0; q < 4; q++) acc[mt][nt][q] = 0.0f;

        // ---- stage 1: B <- Wv image, gather xagg, zero stats, LN params
        copy_img(g_img_v, Bhp, tid);
        {
            const int r = tid >> 1, hf = tid & 1;
            const float4* src = (const float4*)(g_xagg[t] + (size_t)(rb + r) * H) + hf * 16;
            char* ah = Ahp + r * SA + hf * 128;
            char* al = Alp + r * SA + hf * 128;
            #pragma unroll
            for (int j = 0; j < 16; j++) {
                uint32_t hi[2], lo[2];
                split4(__ldg(src + j), hi, lo);
                *(uint32_t*)(ah + j * 8)     = hi[0];
                *(uint32_t*)(ah + j * 8 + 4) = hi[1];
                *(uint32_t*)(al + j * 8)     = lo[0];
                *(uint32_t*)(al + j * 8 + 4) = lo[1];
            }
        }
        if (tid < 256) { sS1[tid] = 0.0f; sS2[tid] = 0.0f; }
        if (tid < H) {
            s_bias[tid] = __ldg(bv + tid) + __ldg(bs + tid);
            s_g[tid] = __ldg(lns + t * H + tid);
            s_b[tid] = __ldg(lnb + t * H + tid);
        }
        __syncthreads();
        MMA_TILE256(AhA, AlA, BhA, BlA, acc, rbw, ch, lane);
        __syncthreads();

        // ---- stage 2: B <- Ws image, gather x (strided from zx rows)
        copy_img(g_img_s, Bhp, tid);
        {
            const int r = tid >> 1, hf = tid & 1;
            const float4* src = (const float4*)(g_zx[t] + (size_t)(rb + r) * ZXW + 64) + hf * 16;
            char* ah = Ahp + r * SA + hf * 128;
            char* al = Alp + r * SA + hf * 128;
            #pragma unroll
            for (int j = 0; j < 16; j++) {
                uint32_t hi[2], lo[2];
                split4(__ldg(src + j), hi, lo);
                *(uint32_t*)(ah + j * 8)     = hi[0];
                *(uint32_t*)(ah + j * 8 + 4) = hi[1];
                *(uint32_t*)(al + j * 8)     = lo[0];
                *(uint32_t*)(al + j * 8 + 4) = lo[1];
            }
        }
        __syncthreads();
        MMA_TILE256(AhA, AlA, BhA, BlA, acc, rbw, ch, lane);

        // ---- bias + LN stats over 256 local rows
        const int lr = lane >> 2;
        #pragma unroll
        for (int mt = 0; mt < 2; mt++) {
            const int row0 = rbw + mt * 16 + lr, row1 = row0 + 8;
            float s1a = 0, s2a = 0, s1b = 0, s2b = 0;
            #pragma unroll
            for (int nt = 0; nt < 8; nt++) {
                const int col = ch * 64 + nt * 8 + (lane & 3) * 2;
                acc[mt][nt][0] += s_bias[col]; acc[mt][nt][1] += s_bias[col + 1];
                acc[mt][nt][2] += s_bias[col]; acc[mt][nt][3] += s_bias[col + 1];
                s1a += acc[mt][nt][0] + acc[mt][nt][1];
                s2a += acc[mt][nt][0] * acc[mt][nt][0] + acc[mt][nt][1] * acc[mt][nt][1];
                s1b += acc[mt][nt][2] + acc[mt][nt][3];
                s2b += acc[mt][nt][2] * acc[mt][nt][2] + acc[mt][nt][3] * acc[mt][nt][3];
            }
            #pragma unroll
            for (int o = 1; o < 4; o <<= 1) {
                s1a += __shfl_xor_sync(0xffffffffu, s1a, o);
                s2a += __shfl_xor_sync(0xffffffffu, s2a, o);
                s1b += __shfl_xor_sync(0xffffffffu, s1b, o);
                s2b += __shfl_xor_sync(0xffffffffu, s2b, o);
            }
            if ((lane & 3) == 0) {
                atomicAdd(&sS1[row0], s1a); atomicAdd(&sS2[row0], s2a);
                atomicAdd(&sS1[row1], s1b); atomicAdd(&sS2[row1], s2b);
            }
        }
        __syncthreads();
        if (tid < 256) {
            const float mu = sS1[tid] * (1.0f / H);
            const float var = sS2[tid] * (1.0f / H) - mu * mu;
            sMu[tid] = mu;
            sRstd[tid] = rsqrtf(var + LN_EPS);
        }
        __syncthreads();

        // ---- stage 3: h -> A tile (split bf16), B <- W1t image
        #pragma unroll
        for (int mt = 0; mt < 2; mt++) {
            const int row0 = rbw + mt * 16 + lr, row1 = row0 + 8;
            const float mu0 = sMu[row0], rs0 = sRstd[row0];
            const float mu1 = sMu[row1], rs1 = sRstd[row1];
            #pragma unroll
            for (int nt = 0; nt < 8; nt++) {
                const int col = ch * 64 + nt * 8 + (lane & 3) * 2;
                const float g0 = s_g[col], g1 = s_g[col + 1];
                const float b0 = s_b[col], b1v = s_b[col + 1];
                const float h00 = (acc[mt][nt][0] - mu0) * rs0 * g0 + b0;
                const float h01 = (acc[mt][nt][1] - mu0) * rs0 * g1 + b1v;
                const float h10 = (acc[mt][nt][2] - mu1) * rs1 * g0 + b0;
                const float h11 = (acc[mt][nt][3] - mu1) * rs1 * g1 + b1v;
                uint32_t hi, lo;
                split2(h00, h01, hi, lo);
                *(uint32_t*)(Ahp + row0 * SA + col * 2) = hi;
                *(uint32_t*)(Alp + row0 * SA + col * 2) = lo;
                split2(h10, h11, hi, lo);
                *(uint32_t*)(Ahp + row1 * SA + col * 2) = hi;
                *(uint32_t*)(Alp + row1 * SA + col * 2) = lo;
            }
        }
        copy_img(g_img_w1[t], Bhp, tid);
        __syncthreads();

        // ---- stage 3 GEMM: hw = h @ W1t
        #pragma unroll
        for (int mt = 0; mt < 2; mt++)
            #pragma unroll
            for (int nt = 0; nt < 8; nt++)
                #pragma unroll
                for (int q = 0; q < 4; q++) acc[mt][nt][q] = 0.0f;
        MMA_TILE256(AhA, AlA, BhA, BlA, acc, rbw, ch, lane);

        #pragma unroll
        for (int mt = 0; mt < 2; mt++) {
            const int row0 = rb + rbw + mt * 16 + lr;
            #pragma unroll
            for (int nt = 0; nt < 8; nt++) {
                const int col = ch * 64 + nt * 8 + (lane & 3) * 2;
                float2 v0 = { acc[mt][nt][0], acc[mt][nt][1] };
                float2 v1 = { acc[mt][nt][2], acc[mt][nt][3] };
                *(float2*)(g_hw[t] + (size_t)row0 * H + col)       = v0;
                *(float2*)(g_hw[t] + (size_t)(row0 + 8) * H + col) = v1;
            }
        }
        __syncthreads();
    }
}

// ====== h1[d] += sum over ALL types of sum_e hw_t[col[e]] (warp per row) =====
__global__ void __launch_bounds__(256) k_h1add_all() {
    const int warp = threadIdx.x >> 5, lane = threadIdx.x & 31;
    const int d = blockIdx.x * 8 + warp;
    float4 acc = {0.0f, 0.0f, 0.0f, 0.0f};
    #pragma unroll 1
    for (int t = 0; t < T_TYPES; t++) {
        const int start = g_ptr[t][d], deg = g_deg[t][d];
        const float* hwt = g_hw[t];
        for (int e = 0; e < deg; e++) {
            const int s = g_col[t][start + e];
            const float4 w4 = ((const float4*)(hwt + (size_t)s * H))[lane];
            acc.x += w4.x; acc.y += w4.y; acc.z += w4.z; acc.w += w4.w;
        }
    }
    float4* p = (float4*)(g_h1 + (size_t)d * H) + lane;
    float4 cur = *p;
    cur.x += acc.x; cur.y += acc.y; cur.z += acc.z; cur.w += acc.w;
    *p = cur;
}

// ===== tail MLP via MMA: out = relu(relu(h1)@W2 + b2) @ W3 + b3 ==============
__global__ void __launch_bounds__(512, 1) k_mlp_mma(
    const float* __restrict__ W2, const float* __restrict__ b2,
    const float* __restrict__ W3, const float* __restrict__ b3,
    float* __restrict__ out) {
    extern __shared__ char dsraw[];
    __shared__ float s_w3[64], s_b2[64], s_out[256];
    const uint32_t raw  = smem_u32(dsraw);
    const uint32_t base = (raw + 1023u) & ~1023u;
    char* dsm = dsraw + (base - raw);
    const int tid = threadIdx.x, warp = tid >> 5, lane = tid & 31;

    char* Ahp = dsm;
    char* Alp = dsm + ATILE2;
    char* Bhp = dsm + 2 * ATILE2;
    char* Blp = Bhp + W2T;
    for (int i = tid; i < 64 * H; i += 512) {
        const int k = i >> 6, n = i & 63;
        const float w = W2[k * 64 + n];
        const __nv_bfloat16 h = __float2bfloat16(w);
        *(__nv_bfloat16*)(Bhp + n * SA + k * 2) = h;
        *(__nv_bfloat16*)(Blp + n * SA + k * 2) = __float2bfloat16(w - __bfloat162float(h));
    }
    if (tid < 64) { s_w3[tid] = W3[tid]; s_b2[tid] = b2[tid]; }
    const float b3v = __ldg(b3);
    __syncthreads();

    const uint32_t AhA = smem_u32(Ahp), AlA = smem_u32(Alp);
    const uint32_t BhA = smem_u32(Bhp), BlA = smem_u32(Blp);
    const int rbw = (warp & 7) * 32;
    const int ch  = warp >> 3;

    for (int tile = blockIdx.x; tile < NUM_TX / 256; tile += gridDim.x) {
        const int rb = tile * 256;
        if (tid < 256) s_out[tid] = 0.0f;
        {
            const int r = tid >> 1, hf = tid & 1;
            const float4* src = (const float4*)(g_h1 + (size_t)(rb + r) * H) + hf * 16;
            char* ah = Ahp + r * SA + hf * 128;
            char* al = Alp + r * SA + hf * 128;
            #pragma unroll
            for (int j = 0; j < 16; j++) {
                float4 v = __ldg(src + j);
                v.x = fmaxf(v.x, 0.0f); v.y = fmaxf(v.y, 0.0f);
                v.z = fmaxf(v.z, 0.0f); v.w = fmaxf(v.w, 0.0f);
                uint32_t hi[2], lo[2];
                split4(v, hi, lo);
                *(uint32_t*)(ah + j * 8)     = hi[0];
                *(uint32_t*)(ah + j * 8 + 4) = hi[1];
                *(uint32_t*)(al + j * 8)     = lo[0];
                *(uint32_t*)(al + j * 8 + 4) = lo[1];
            }
        }
        __syncthreads();

        float acc[2][4][4];
        #pragma unroll
        for (int mt = 0; mt < 2; mt++)
            #pragma unroll
            for (int nt = 0; nt < 4; nt++)
                #pragma unroll
                for (int q = 0; q < 4; q++) acc[mt][nt][q] = 0.0f;

        {
            const uint32_t arow = rbw + (lane & 15);
            const uint32_t aqof = (lane >> 4) * 16;
            const uint32_t brow = ch * 32 + ((lane >> 4) * 8) + (lane & 7);
            const uint32_t bqof = ((lane >> 3) & 1) * 16;
            #pragma unroll
            for (int ks = 0; ks < 8; ks++) {
                const uint32_t kb = ks * 32;
                uint32_t ah[2][4], al[2][4], bh_[2][4], bl_[2][4];
                #pragma unroll
                for (int mt = 0; mt < 2; mt++) {
                    const uint32_t ao = (arow + mt * 16) * SA + kb + aqof;
                    ldmx4(ah[mt], AhA + ao);
                    ldmx4(al[mt], AlA + ao);
                }
                #pragma unroll
                for (int np = 0; np < 2; np++) {
                    const uint32_t bo = (brow + np * 16) * SA + kb + bqof;
                    ldmx4(bh_[np], BhA + bo);
                    ldmx4(bl_[np], BlA + bo);
                }
                #pragma unroll
                for (int np = 0; np < 2; np++)
                    #pragma unroll
                    for (int sb = 0; sb < 2; sb++) {
                        const int nt = np * 2 + sb;
                        #pragma unroll
                        for (int mt = 0; mt < 2; mt++) {
                            mma_bf16(acc[mt][nt], ah[mt], bh_[np][sb*2], bh_[np][sb*2+1]);
                            mma_bf16(acc[mt][nt], al[mt], bh_[np][sb*2], bh_[np][sb*2+1]);
                            mma_bf16(acc[mt][nt], ah[mt], bl_[np][sb*2], bl_[np][sb*2+1]);
                        }
                    }
            }
        }

        #pragma unroll
        for (int mt = 0; mt < 2; mt++) {
            const int row0 = rbw + mt * 16 + (lane >> 2), row1 = row0 + 8;
            float p0 = 0.0f, p1 = 0.0f;
            #pragma unroll
            for (int nt = 0; nt < 4; nt++) {
                const int col = ch * 32 + nt * 8 + (lane & 3) * 2;
                p0 += fmaxf(acc[mt][nt][0] + s_b2[col],     0.0f) * s_w3[col]
                    + fmaxf(acc[mt][nt][1] + s_b2[col + 1], 0.0f) * s_w3[col + 1];
                p1 += fmaxf(acc[mt][nt][2] + s_b2[col],     0.0f) * s_w3[col]
                    + fmaxf(acc[mt][nt][3] + s_b2[col + 1], 0.0f) * s_w3[col + 1];
            }
            #pragma unroll
            for (int o = 1; o < 4; o <<= 1) {
                p0 += __shfl_xor_sync(0xffffffffu, p0, o);
                p1 += __shfl_xor_sync(0xffffffffu, p1, o);
            }
            if ((lane & 3) == 0) {
                atomicAdd(&s_out[row0], p0);
                atomicAdd(&s_out[row1], p1);
            }
        }
        __syncthreads();
        if (tid < 256) out[rb + tid] = s_out[tid] + b3v;
        __syncthreads();
    }
}

// ================= host launcher =============================================
extern "C" void kernel_launch(void* const* d_in, const int* in_sizes, int n_in,
                              void* d_out, int out_size) {
    const float* tx_x = (const float*)d_in[0];
    const float* emb  = (const float*)d_in[1];
    const int*   eidx = (const int*)  d_in[2];
    const int*   esrc = (const int*)  d_in[3];
    const int*   edst = (const int*)  d_in[4];
    const float* Wq = (const float*)d_in[5],  *bq = (const float*)d_in[6];
    const float* Wk = (const float*)d_in[7];
    const float* Wv = (const float*)d_in[9],  *bv = (const float*)d_in[10];
    const float* Ws = (const float*)d_in[11], *bs = (const float*)d_in[12];
    const float* lns = (const float*)d_in[13], *lnb = (const float*)d_in[14];
    const float* W1 = (const float*)d_in[15], *b1 = (const float*)d_in[16];
    const float* W2 = (const float*)d_in[17], *b2 = (const float*)d_in[18];
    const float* W3 = (const float*)d_in[19], *b3 = (const float*)d_in[20];
    float* out = (float*)d_out;

    const int SM256    = 2 * ATILE2 + 2 * BTILE + 1024;  // 209920
    const int MLP_SMEM = 2 * ATILE2 + 2 * W2T + 1024;    // 175104
    cudaFuncSetAttribute(k_init_mma, cudaFuncAttributeMaxDynamicSharedMemorySize, SM256);
    cudaFuncSetAttribute(k_z_mma,    cudaFuncAttributeMaxDynamicSharedMemorySize, SM256);
    cudaFuncSetAttribute(k_fused,    cudaFuncAttributeMaxDynamicSharedMemorySize, SM256);
    cudaFuncSetAttribute(k_mlp_mma,  cudaFuncAttributeMaxDynamicSharedMemorySize, MLP_SMEM);

    k_prep <<<128, 128>>>(Wq, Wk, bq);
    k_mkimg<<<2 + T_TYPES, 256>>>(Wv, Ws, W1);

    k_zero_deg<<<(T_TYPES * N_ENT + 255) / 256, 256>>>();
    k_count   <<<(T_TYPES * NE + 255) / 256, 256>>>(edst);
    k_scan    <<<T_TYPES, 1024>>>();
    k_fill    <<<(T_TYPES * NE + 255) / 256, 256>>>(esrc, edst);

    k_init_mma<<<148, 512, SM256>>>(tx_x, W1, b1);

    k_z_mma  <<<148, 512, SM256>>>(emb, eidx);
    k_attn   <<<T_TYPES * (N_ENT / 8), 256>>>();
    k_fused  <<<148, 512, SM256>>>(bv, bs, lns, lnb);
    k_h1add_all<<<NUM_TX / 8, 256>>>();

    k_mlp_mma<<<148, 512, MLP_SMEM>>>(W2, b2, W3, b3, out);
}

// round 13
// speedup vs baseline: 1.0000x; 1.0000x over previous
#include <cuda_runtime.h>
#include <cuda_bf16.h>
#include <math.h>
#include <stdint.h>

#define T_TYPES 11
#define NUM_TX  131072
#define N_ENT   131072
#define NE      262144
#define H       128
#define TXF     394
#define LN_EPS  1e-5f
#define INV_SQRT_D 0.08838834764831845f   // 1/sqrt(128)

// bf16 tile strides (bytes): 128 bf16 = 256B + 16B pad -> conflict-free ldmatrix
#define SA 272
#define ATILE2  69632     // 256 rows * 272B
#define BTILE   34816     // 128 n-rows * 272B
#define W2T     17408     // 64 n-rows * 272B

// ---------------- scratch (device globals; no cudaMalloc allowed) ----------
__device__ uint32_t g_zb [T_TYPES][(size_t)N_ENT * 64];  // bf16x2 z rows
__device__ float g_x   [T_TYPES][(size_t)N_ENT * H];
__device__ float g_xagg[T_TYPES][(size_t)N_ENT * H];
__device__ float g_hw  [T_TYPES][(size_t)N_ENT * H];
__device__ float g_c   [T_TYPES][N_ENT];
__device__ float g_h1  [(size_t)NUM_TX * H];
__device__ float g_weff[H * H];               // Wz[k][n]
__device__ float g_wkbq[H];

// precomputed split-bf16 swizzled B images: [hi BTILE][lo BTILE]
__device__ uint4 g_img_v [(2 * BTILE) / 16];
__device__ uint4 g_img_s [(2 * BTILE) / 16];
__device__ uint4 g_img_w1[T_TYPES][(2 * BTILE) / 16];

// CSR over dst, per type
__device__ int g_deg [T_TYPES][N_ENT];
__device__ int g_ptr [T_TYPES][N_ENT];
__device__ int g_cur [T_TYPES][N_ENT];
__device__ int g_col [T_TYPES][NE];

// ================= helpers ===================================================
__device__ __forceinline__ uint32_t smem_u32(const void* p) {
    uint32_t a;
    asm("{ .reg .u64 t; cvta.to.shared.u64 t, %1; cvt.u32.u64 %0, t; }" : "=r"(a) : "l"(p));
    return a;
}
__device__ __forceinline__ void ldmx4(uint32_t* r, uint32_t addr) {
    asm volatile("ldmatrix.sync.aligned.m8n8.x4.shared.b16 {%0,%1,%2,%3}, [%4];"
        : "=r"(r[0]), "=r"(r[1]), "=r"(r[2]), "=r"(r[3]) : "r"(addr));
}
__device__ __forceinline__ void mma_bf16(float* c, const uint32_t* a, uint32_t b0, uint32_t b1) {
    asm volatile("mma.sync.aligned.m16n8k16.row.col.f32.bf16.bf16.f32 "
        "{%0,%1,%2,%3}, {%4,%5,%6,%7}, {%8,%9}, {%0,%1,%2,%3};"
        : "+f"(c[0]), "+f"(c[1]), "+f"(c[2]), "+f"(c[3])
        : "r"(a[0]), "r"(a[1]), "r"(a[2]), "r"(a[3]), "r"(b0), "r"(b1));
}
__device__ __forceinline__ uint32_t bfpack(float a, float b) {
    __nv_bfloat162 t = __floats2bfloat162_rn(a, b);
    return reinterpret_cast<uint32_t&>(t);
}
__device__ __forceinline__ void split4(float4 v, uint32_t* hi, uint32_t* lo) {
    __nv_bfloat16 hx = __float2bfloat16(v.x), hy = __float2bfloat16(v.y);
    __nv_bfloat16 hz = __float2bfloat16(v.z), hw = __float2bfloat16(v.w);
    __nv_bfloat162 h01; h01.x = hx; h01.y = hy;
    __nv_bfloat162 h23; h23.x = hz; h23.y = hw;
    hi[0] = reinterpret_cast<uint32_t&>(h01);
    hi[1] = reinterpret_cast<uint32_t&>(h23);
    lo[0] = bfpack(v.x - __bfloat162float(hx), v.y - __bfloat162float(hy));
    lo[1] = bfpack(v.z - __bfloat162float(hz), v.w - __bfloat162float(hw));
}
__device__ __forceinline__ void split2(float a, float b, uint32_t& hi, uint32_t& lo) {
    __nv_bfloat16 ha = __float2bfloat16(a), hb = __float2bfloat16(b);
    __nv_bfloat162 hp; hp.x = ha; hp.y = hb;
    hi = reinterpret_cast<uint32_t&>(hp);
    lo = bfpack(a - __bfloat162float(ha), b - __bfloat162float(hb));
}
__device__ __forceinline__ void conv_B(const float* __restrict__ W, char* bh, char* bl,
                                       int tid, int nthr) {
    for (int i = tid; i < H * H; i += nthr) {
        const int k = i >> 7, n = i & 127;
        const float w = W[i];
        const __nv_bfloat16 h = __float2bfloat16(w);
        *(__nv_bfloat16*)(bh + n * SA + k * 2) = h;
        *(__nv_bfloat16*)(bl + n * SA + k * 2) = __float2bfloat16(w - __bfloat162float(h));
    }
}
__device__ __forceinline__ void copy_img(const uint4* __restrict__ img, char* bh, int tid) {
    uint4* d = (uint4*)bh;
    for (int i = tid; i < (2 * BTILE) / 16; i += 512) d[i] = __ldg(img + i);
}

// ================= prep: Wz = Wk Wq^T, wkbq = Wk bq ==========================
__global__ void k_prep(const float* __restrict__ Wq, const float* __restrict__ Wk,
                       const float* __restrict__ bq) {
    __shared__ float wkrow[H];
    const int b = blockIdx.x, a = threadIdx.x;
    wkrow[a] = Wk[b * H + a];
    __syncthreads();
    float s = 0.0f;
    #pragma unroll 4
    for (int j = 0; j < H; j++) s = fmaf(wkrow[j], Wq[a * H + j], s);
    g_weff[b * H + a] = s;
    if (b == 0) {
        float t = 0.0f;
        for (int j = 0; j < H; j++) t = fmaf(Wk[a * H + j], bq[j], t);
        g_wkbq[a] = t;
    }
}

// ================= build split-bf16 B images =================================
__global__ void k_mkimg(const float* __restrict__ Wv, const float* __restrict__ Ws,
                        const float* __restrict__ W1) {
    const int b = blockIdx.x;
    const float* W;
    uint8_t* img;
    if (b == 0)      { W = Wv; img = (uint8_t*)g_img_v; }
    else if (b == 1) { W = Ws; img = (uint8_t*)g_img_s; }
    else             { W = W1 + (size_t)(TXF + (b - 2) * H) * H;
                       img = (uint8_t*)g_img_w1[b - 2]; }
    for (int i = threadIdx.x; i < H * H; i += 256) {
        const int k = i >> 7, n = i & 127;
        const float w = W[i];
        const __nv_bfloat16 h = __float2bfloat16(w);
        *(__nv_bfloat16*)(img + n * SA + k * 2) = h;
        *(__nv_bfloat16*)(img + BTILE + n * SA + k * 2) =
            __float2bfloat16(w - __bfloat162float(h));
    }
}

// ================= CSR build =================================================
__global__ void k_zero_deg() {
    const int i = blockIdx.x * blockDim.x + threadIdx.x;
    if (i < T_TYPES * N_ENT) ((int*)g_deg)[i] = 0;
}
__global__ void k_count(const int* __restrict__ edst) {
    const int i = blockIdx.x * blockDim.x + threadIdx.x;
    if (i >= T_TYPES * NE) return;
    const int t = i / NE;
    atomicAdd(&g_deg[t][edst[i]], 1);
}
// one block per type: 1024 threads, each scans 128 contiguous entries
__global__ void __launch_bounds__(1024) k_scan() {
    const int t = blockIdx.x, tid = threadIdx.x;
    const int base = tid * 128;
    int s = 0;
    for (int j = 0; j < 128; j++) s += g_deg[t][base + j];
    __shared__ int sm[1024];
    sm[tid] = s; __syncthreads();
    for (int off = 1; off < 1024; off <<= 1) {
        int x = (tid >= off) ? sm[tid - off] : 0;
        __syncthreads();
        sm[tid] += x;
        __syncthreads();
    }
    int run = (tid == 0) ? 0 : sm[tid - 1];
    for (int j = 0; j < 128; j++) {
        const int i = base + j;
        g_ptr[t][i] = run;
        g_cur[t][i] = run;
        run += g_deg[t][i];
    }
}
__global__ void k_fill(const int* __restrict__ esrc, const int* __restrict__ edst) {
    const int i = blockIdx.x * blockDim.x + threadIdx.x;
    if (i >= T_TYPES * NE) return;
    const int t = i / NE;
    const int slot = atomicAdd(&g_cur[t][edst[i]], 1);
    g_col[t][slot] = esrc[i];
}

// ================= MMA core (256-row tile, acc[2][8][4], 16 warps) ==========
#define MMA_TILE256(AhA, AlA, BhA, BlA, acc, rbw, ch, lane)                          \
    {                                                                                 \
        const uint32_t arow = (rbw) + ((lane) & 15);                                  \
        const uint32_t aqof = ((lane) >> 4) * 16;                                     \
        const uint32_t brow = (ch) * 64 + (((lane) >> 4) * 8) + ((lane) & 7);         \
        const uint32_t bqof = (((lane) >> 3) & 1) * 16;                               \
        _Pragma("unroll")                                                             \
        for (int ks = 0; ks < 8; ks++) {                                              \
            const uint32_t kb = ks * 32;                                              \
            uint32_t ah[2][4], al[2][4], bf[4][4];                                    \
            _Pragma("unroll")                                                         \
            for (int mt = 0; mt < 2; mt++) {                                          \
                const uint32_t ao = (arow + mt * 16) * SA + kb + aqof;                \
                ldmx4(ah[mt], (AhA) + ao);                                            \
                ldmx4(al[mt], (AlA) + ao);                                            \
            }                                                                         \
            _Pragma("unroll")                                                         \
            for (int np = 0; np < 4; np++)                                            \
                ldmx4(bf[np], (BhA) + (brow + np * 16) * SA + kb + bqof);             \
            _Pragma("unroll")                                                         \
            for (int np = 0; np < 4; np++)                                            \
                _Pragma("unroll")                                                     \
                for (int sb = 0; sb < 2; sb++) {                                      \
                    const int nt = np * 2 + sb;                                       \
                    _Pragma("unroll")                                                 \
                    for (int mt = 0; mt < 2; mt++) {                                  \
                        mma_bf16(acc[mt][nt], ah[mt], bf[np][sb*2], bf[np][sb*2+1]);  \
                        mma_bf16(acc[mt][nt], al[mt], bf[np][sb*2], bf[np][sb*2+1]);  \
                    }                                                                 \
                }                                                                     \
            _Pragma("unroll")                                                         \
            for (int np = 0; np < 4; np++)                                            \
                ldmx4(bf[np], (BlA) + (brow + np * 16) * SA + kb + bqof);             \
            _Pragma("unroll")                                                         \
            for (int np = 0; np < 4; np++)                                            \
                _Pragma("unroll")                                                     \
                for (int sb = 0; sb < 2; sb++) {                                      \
                    const int nt = np * 2 + sb;                                       \
                    _Pragma("unroll")                                                 \
                    for (int mt = 0; mt < 2; mt++)                                    \
                        mma_bf16(acc[mt][nt], ah[mt], bf[np][sb*2], bf[np][sb*2+1]);  \
                }                                                                     \
        }                                                                             \
    }

// ================= init_h1 via MMA: b1 + tx_x @ W1[0:394] ====================
__global__ void __launch_bounds__(512, 1) k_init_mma(const float* __restrict__ tx,
                                                     const float* __restrict__ W1,
                                                     const float* __restrict__ b1) {
    extern __shared__ char dsraw[];
    __shared__ float s_b1[H];
    const uint32_t raw  = smem_u32(dsraw);
    const uint32_t base = (raw + 1023u) & ~1023u;
    char* dsm = dsraw + (base - raw);
    const int tid = threadIdx.x, warp = tid >> 5, lane = tid & 31;

    char* Ahp = dsm;
    char* Alp = dsm + ATILE2;
    char* Bhp = dsm + 2 * ATILE2;
    char* Blp = Bhp + BTILE;
    const uint32_t AhA = smem_u32(Ahp), AlA = smem_u32(Alp);
    const uint32_t BhA = smem_u32(Bhp), BlA = smem_u32(Blp);

    if (tid < H) s_b1[tid] = b1[tid];

    const int rbw = (warp & 7) * 32;
    const int ch  = warp >> 3;

    for (int tile = blockIdx.x; tile < NUM_TX / 256; tile += gridDim.x) {
        const int rb = tile * 256;
        float acc[2][8][4];
        #pragma unroll
        for (int mt = 0; mt < 2; mt++)
            #pragma unroll
            for (int nt = 0; nt < 8; nt++)
                #pragma unroll
                for (int q = 0; q < 4; q++) acc[mt][nt][q] = 0.0f;

        for (int chunk = 0; chunk < 4; chunk++) {
            __syncthreads();
            const int kcols = (chunk < 3) ? 128 : 16;
            for (int i = tid; i < kcols * H; i += 512) {
                const int k = i >> 7, n = i & 127;
                const int kk = chunk * 128 + k;
                const float w = (kk < TXF) ? W1[(size_t)kk * H + n] : 0.0f;
                const __nv_bfloat16 h = __float2bfloat16(w);
                *(__nv_bfloat16*)(Bhp + n * SA + k * 2) = h;
                *(__nv_bfloat16*)(Blp + n * SA + k * 2) =
                    __float2bfloat16(w - __bfloat162float(h));
            }
            const int r = tid >> 1, hf = tid & 1;
            const float* rowp = tx + (size_t)(rb + r) * TXF;
            if (chunk < 3) {
                const float2* src = (const float2*)(rowp + chunk * 128 + hf * 64);
                char* ah = Ahp + r * SA + hf * 128;
                char* al = Alp + r * SA + hf * 128;
                #pragma unroll
                for (int j = 0; j < 16; j++) {
                    const float2 a = __ldg(src + j * 2);
                    const float2 b = __ldg(src + j * 2 + 1);
                    float4 v = { a.x, a.y, b.x, b.y };
                    uint32_t hi[2], lo[2];
                    split4(v, hi, lo);
                    *(uint32_t*)(ah + j * 8)     = hi[0];
                    *(uint32_t*)(ah + j * 8 + 4) = hi[1];
                    *(uint32_t*)(al + j * 8)     = lo[0];
                    *(uint32_t*)(al + j * 8 + 4) = lo[1];
                }
            } else {
                float vals[8];
                #pragma unroll
                for (int j = 0; j < 8; j++) {
                    const int c = 384 + hf * 8 + j;
                    vals[j] = (c < TXF) ? __ldg(rowp + c) : 0.0f;
                }
                char* ah = Ahp + r * SA + hf * 16;
                char* al = Alp + r * SA + hf * 16;
                #pragma unroll
                for (int p = 0; p < 4; p++) {
                    float4 v = { vals[p*2], vals[p*2+1], 0.0f, 0.0f };
                    uint32_t hi[2], lo[2];
                    split4(v, hi, lo);
                    *(uint32_t*)(ah + p * 4) = hi[0];
                    *(uint32_t*)(al + p * 4) = lo[0];
                }
            }
            __syncthreads();

            const uint32_t arow = rbw + (lane & 15);
            const uint32_t aqof = (lane >> 4) * 16;
            const uint32_t brow = ch * 64 + ((lane >> 4) * 8) + (lane & 7);
            const uint32_t bqof = ((lane >> 3) & 1) * 16;
            const int nks = (chunk < 3) ? 8 : 1;
            for (int ks = 0; ks < nks; ks++) {
                const uint32_t kb = ks * 32;
                uint32_t ah[2][4], al[2][4], bf[4][4];
                #pragma unroll
                for (int mt = 0; mt < 2; mt++) {
                    const uint32_t ao = (arow + mt * 16) * SA + kb + aqof;
                    ldmx4(ah[mt], AhA + ao);
                    ldmx4(al[mt], AlA + ao);
                }
                #pragma unroll
                for (int np = 0; np < 4; np++)
                    ldmx4(bf[np], BhA + (brow + np * 16) * SA + kb + bqof);
                #pragma unroll
                for (int np = 0; np < 4; np++)
                    #pragma unroll
                    for (int sb = 0; sb < 2; sb++) {
                        const int nt = np * 2 + sb;
                        #pragma unroll
                        for (int mt = 0; mt < 2; mt++) {
                            mma_bf16(acc[mt][nt], ah[mt], bf[np][sb*2], bf[np][sb*2+1]);
                            mma_bf16(acc[mt][nt], al[mt], bf[np][sb*2], bf[np][sb*2+1]);
                        }
                    }
                #pragma unroll
                for (int np = 0; np < 4; np++)
                    ldmx4(bf[np], BlA + (brow + np * 16) * SA + kb + bqof);
                #pragma unroll
                for (int np = 0; np < 4; np++)
                    #pragma unroll
                    for (int sb = 0; sb < 2; sb++) {
                        const int nt = np * 2 + sb;
                        #pragma unroll
                        for (int mt = 0; mt < 2; mt++)
                            mma_bf16(acc[mt][nt], ah[mt], bf[np][sb*2], bf[np][sb*2+1]);
                    }
            }
        }
        #pragma unroll
        for (int mt = 0; mt < 2; mt++) {
            const int row0 = rb + rbw + mt * 16 + (lane >> 2);
            #pragma unroll
            for (int nt = 0; nt < 8; nt++) {
                const int col = ch * 64 + nt * 8 + (lane & 3) * 2;
                const float b0 = s_b1[col], b1v = s_b1[col + 1];
                float2 v0 = { acc[mt][nt][0] + b0, acc[mt][nt][1] + b1v };
                float2 v1 = { acc[mt][nt][2] + b0, acc[mt][nt][3] + b1v };
                *(float2*)(g_h1 + (size_t)row0 * H + col)       = v0;
                *(float2*)(g_h1 + (size_t)(row0 + 8) * H + col) = v1;
            }
        }
    }
}

// ====== Z GEMM (ALL types): gather x, zb = bf16(x@Wz), c = x.wkbq ============
__global__ void __launch_bounds__(512, 1) k_z_mma(const float* __restrict__ emb,
                                                  const int* __restrict__ idx) {
    extern __shared__ char dsraw[];
    __shared__ float s_wkbq[H];
    const uint32_t raw  = smem_u32(dsraw);
    const uint32_t base = (raw + 1023u) & ~1023u;
    char* dsm = dsraw + (base - raw);
    const int tid = threadIdx.x, warp = tid >> 5, lane = tid & 31;

    char* Ahp = dsm;
    char* Alp = dsm + ATILE2;
    char* Bhp = dsm + 2 * ATILE2;
    char* Blp = Bhp + BTILE;
    conv_B(g_weff, Bhp, Blp, tid, 512);
    if (tid < H) s_wkbq[tid] = g_wkbq[tid];
    __syncthreads();

    const uint32_t AhA = smem_u32(Ahp), AlA = smem_u32(Alp);
    const uint32_t BhA = smem_u32(Bhp), BlA = smem_u32(Blp);
    const int rbw = (warp & 7) * 32;
    const int ch  = warp >> 3;

    for (int tile = blockIdx.x; tile < T_TYPES * (N_ENT / 256); tile += gridDim.x) {
        const int t  = tile >> 9;                 // 512 tiles per type
        const int rb = (tile & 511) * 256;
        const float* embt = emb + (size_t)t * N_ENT * H;
        const int*   idxt = idx + (size_t)t * N_ENT;
        {
            const int r = tid >> 1, hf = tid & 1;
            const int e = __ldg(idxt + rb + r);
            const float4* src = (const float4*)(embt + (size_t)e * H) + hf * 16;
            float4* xdst = (float4*)(g_x[t] + (size_t)(rb + r) * H) + hf * 16;
            char* ah = Ahp + r * SA + hf * 128;
            char* al = Alp + r * SA + hf * 128;
            float cp = 0.0f;
            #pragma unroll
            for (int j = 0; j < 16; j++) {
                const float4 v = __ldg(src + j);
                uint32_t hi[2], lo[2];
                split4(v, hi, lo);
                *(uint32_t*)(ah + j * 8)     = hi[0];
                *(uint32_t*)(ah + j * 8 + 4) = hi[1];
                *(uint32_t*)(al + j * 8)     = lo[0];
                *(uint32_t*)(al + j * 8 + 4) = lo[1];
                xdst[j] = v;
                const float* wb = s_wkbq + hf * 64 + j * 4;
                cp += v.x * wb[0] + v.y * wb[1] + v.z * wb[2] + v.w * wb[3];
            }
            cp += __shfl_xor_sync(0xffffffffu, cp, 1);
            if (hf == 0) g_c[t][rb + r] = cp;
        }
        __syncthreads();

        float acc[2][8][4];
        #pragma unroll
        for (int mt = 0; mt < 2; mt++)
            #pragma unroll
            for (int nt = 0; nt < 8; nt++)
                #pragma unroll
                for (int q = 0; q < 4; q++) acc[mt][nt][q] = 0.0f;

        MMA_TILE256(AhA, AlA, BhA, BlA, acc, rbw, ch, lane);

        #pragma unroll
        for (int mt = 0; mt < 2; mt++) {
            const int row0 = rb + rbw + mt * 16 + (lane >> 2);
            #pragma unroll
            for (int nt = 0; nt < 8; nt++) {
                const int col = ch * 64 + nt * 8 + (lane & 3) * 2;
                g_zb[t][(size_t)row0 * 64 + (col >> 1)] =
                    bfpack(acc[mt][nt][0], acc[mt][nt][1]);
                g_zb[t][(size_t)(row0 + 8) * 64 + (col >> 1)] =
                    bfpack(acc[mt][nt][2], acc[mt][nt][3]);
            }
        }
        __syncthreads();
    }
}

// ================= attention aggregation (ALL types; warp per dst) ===========
__global__ void __launch_bounds__(256) k_attn() {
    const int warp = threadIdx.x >> 5, lane = threadIdx.x & 31;
    const int t = blockIdx.x >> 14;               // 16384 blocks per type
    const int d = (blockIdx.x & 16383) * 8 + warp;
    const float4 xd4 = ((const float4*)(g_x[t] + (size_t)d * H))[lane];
    const int start = g_ptr[t][d], deg = g_deg[t][d];

    float den = 0.0f;
    float4 acc = {0.0f, 0.0f, 0.0f, 0.0f};
    for (int e = 0; e < deg; e++) {
        const int s = g_col[t][start + e];
        const uint2 z2 = *((const uint2*)(g_zb[t] + (size_t)s * 64) + lane);
        const float2 z0 = __bfloat1622float2(*(const __nv_bfloat162*)&z2.x);
        const float2 z1 = __bfloat1622float2(*(const __nv_bfloat162*)&z2.y);
        const float4 x4 = ((const float4*)(g_x[t] + (size_t)s * H))[lane];
        float dot = xd4.x * z0.x + xd4.y * z0.y + xd4.z * z1.x + xd4.w * z1.y;
        #pragma unroll
        for (int o = 16; o; o >>= 1) dot += __shfl_xor_sync(0xffffffffu, dot, o);
        const float w = expf((dot + __ldg(&g_c[t][s])) * INV_SQRT_D);
        den += w;
        acc.x += w * x4.x; acc.y += w * x4.y; acc.z += w * x4.z; acc.w += w * x4.w;
    }
    const float inv = (deg > 0) ? 1.0f / den : 0.0f;
    float4 o4 = { acc.x * inv, acc.y * inv, acc.z * inv, acc.w * inv };
    ((float4*)(g_xagg[t] + (size_t)d * H))[lane] = o4;
}

// ===== fused (ALL types): h = LN(xagg@Wv + x@Ws + bv+bs)*g+b; hw = h@W1_t ====
__global__ void __launch_bounds__(512, 1) k_fused(
    const float* __restrict__ bv, const float* __restrict__ bs,
    const float* __restrict__ lns, const float* __restrict__ lnb) {
    extern __shared__ char dsraw[];
    __shared__ float s_bias[H], s_g[H], s_b[H];
    __shared__ float sS1[256], sS2[256], sMu[256], sRstd[256];
    const uint32_t raw  = smem_u32(dsraw);
    const uint32_t base = (raw + 1023u) & ~1023u;
    char* dsm = dsraw + (base - raw);
    const int tid = threadIdx.x, warp = tid >> 5, lane = tid & 31;

    char* Ahp = dsm;
    char* Alp = dsm + ATILE2;
    char* Bhp = dsm + 2 * ATILE2;
    const uint32_t AhA = smem_u32(Ahp), AlA = smem_u32(Alp);
    const uint32_t BhA = smem_u32(Bhp), BlA = BhA + BTILE;
    const int rbw = (warp & 7) * 32;
    const int ch  = warp >> 3;

    for (int tile = blockIdx.x; tile < T_TYPES * (N_ENT / 256); tile += gridDim.x) {
        const int t  = tile >> 9;
        const int rb = (tile & 511) * 256;
        float acc[2][8][4];
        #pragma unroll
        for (int mt = 0; mt < 2; mt++)
            #pragma unroll
            for (int nt = 0; nt < 8; nt++)
                #pragma unroll
                for (int q = 0; q < 4; q++) acc[mt][nt][q] = 0.0f;

        // ---- stage 1: B <- Wv image, gather xagg, zero stats, LN params
        copy_img(g_img_v, Bhp, tid);
        {
            const int r = tid >> 1, hf = tid & 1;
            const float4* src = (const float4*)(g_xagg[t] + (size_t)(rb + r) * H) + hf * 16;
            char* ah = Ahp + r * SA + hf * 128;
            char* al = Alp + r * SA + hf * 128;
            #pragma unroll
            for (int j = 0; j < 16; j++) {
                uint32_t hi[2], lo[2];
                split4(__ldg(src + j), hi, lo);
                *(uint32_t*)(ah + j * 8)     = hi[0];
                *(uint32_t*)(ah + j * 8 + 4) = hi[1];
                *(uint32_t*)(al + j * 8)     = lo[0];
                *(uint32_t*)(al + j * 8 + 4) = lo[1];
            }
        }
        if (tid < 256) { sS1[tid] = 0.0f; sS2[tid] = 0.0f; }
        if (tid < H) {
            s_bias[tid] = __ldg(bv + tid) + __ldg(bs + tid);
            s_g[tid] = __ldg(lns + t * H + tid);
            s_b[tid] = __ldg(lnb + t * H + tid);
        }
        __syncthreads();
        MMA_TILE256(AhA, AlA, BhA, BlA, acc, rbw, ch, lane);
        __syncthreads();

        // ---- stage 2: B <- Ws image, gather x
        copy_img(g_img_s, Bhp, tid);
        {
            const int r = tid >> 1, hf = tid & 1;
            const float4* src = (const float4*)(g_x[t] + (size_t)(rb + r) * H) + hf * 16;
            char* ah = Ahp + r * SA + hf * 128;
            char* al = Alp + r * SA + hf * 128;
            #pragma unroll
            for (int j = 0; j < 16; j++) {
                uint32_t hi[2], lo[2];
                split4(__ldg(src + j), hi, lo);
                *(uint32_t*)(ah + j * 8)     = hi[0];
                *(uint32_t*)(ah + j * 8 + 4) = hi[1];
                *(uint32_t*)(al + j * 8)     = lo[0];
                *(uint32_t*)(al + j * 8 + 4) = lo[1];
            }
        }
        __syncthreads();
        MMA_TILE256(AhA, AlA, BhA, BlA, acc, rbw, ch, lane);

        // ---- bias + LN stats over 256 local rows
        const int lr = lane >> 2;
        #pragma unroll
        for (int mt = 0; mt < 2; mt++) {
            const int row0 = rbw + mt * 16 + lr, row1 = row0 + 8;
            float s1a = 0, s2a = 0, s1b = 0, s2b = 0;
            #pragma unroll
            for (int nt = 0; nt < 8; nt++) {
                const int col = ch * 64 + nt * 8 + (lane & 3) * 2;
                acc[mt][nt][0] += s_bias[col]; acc[mt][nt][1] += s_bias[col + 1];
                acc[mt][nt][2] += s_bias[col]; acc[mt][nt][3] += s_bias[col + 1];
                s1a += acc[mt][nt][0] + acc[mt][nt][1];
                s2a += acc[mt][nt][0] * acc[mt][nt][0] + acc[mt][nt][1] * acc[mt][nt][1];
                s1b += acc[mt][nt][2] + acc[mt][nt][3];
                s2b += acc[mt][nt][2] * acc[mt][nt][2] + acc[mt][nt][3] * acc[mt][nt][3];
            }
            #pragma unroll
            for (int o = 1; o < 4; o <<= 1) {
                s1a += __shfl_xor_sync(0xffffffffu, s1a, o);
                s2a += __shfl_xor_sync(0xffffffffu, s2a, o);
                s1b += __shfl_xor_sync(0xffffffffu, s1b, o);
                s2b += __shfl_xor_sync(0xffffffffu, s2b, o);
            }
            if ((lane & 3) == 0) {
                atomicAdd(&sS1[row0], s1a); atomicAdd(&sS2[row0], s2a);
                atomicAdd(&sS1[row1], s1b); atomicAdd(&sS2[row1], s2b);
            }
        }
        __syncthreads();
        if (tid < 256) {
            const float mu = sS1[tid] * (1.0f / H);
            const float var = sS2[tid] * (1.0f / H) - mu * mu;
            sMu[tid] = mu;
            sRstd[tid] = rsqrtf(var + LN_EPS);
        }
        __syncthreads();

        // ---- stage 3: h -> A tile (split bf16), B <- W1t image
        #pragma unroll
        for (int mt = 0; mt < 2; mt++) {
            const int row0 = rbw + mt * 16 + lr, row1 = row0 + 8;
            const float mu0 = sMu[row0], rs0 = sRstd[row0];
            const float mu1 = sMu[row1], rs1 = sRstd[row1];
            #pragma unroll
            for (int nt = 0; nt < 8; nt++) {
                const int col = ch * 64 + nt * 8 + (lane & 3) * 2;
                const float g0 = s_g[col], g1 = s_g[col + 1];
                const float b0 = s_b[col], b1v = s_b[col + 1];
                const float h00 = (acc[mt][nt][0] - mu0) * rs0 * g0 + b0;
                const float h01 = (acc[mt][nt][1] - mu0) * rs0 * g1 + b1v;
                const float h10 = (acc[mt][nt][2] - mu1) * rs1 * g0 + b0;
                const float h11 = (acc[mt][nt][3] - mu1) * rs1 * g1 + b1v;
                uint32_t hi, lo;
                split2(h00, h01, hi, lo);
                *(uint32_t*)(Ahp + row0 * SA + col * 2) = hi;
                *(uint32_t*)(Alp + row0 * SA + col * 2) = lo;
                split2(h10, h11, hi, lo);
                *(uint32_t*)(Ahp + row1 * SA + col * 2) = hi;
                *(uint32_t*)(Alp + row1 * SA + col * 2) = lo;
            }
        }
        copy_img(g_img_w1[t], Bhp, tid);
        __syncthreads();

        // ---- stage 3 GEMM: hw = h @ W1t
        #pragma unroll
        for (int mt = 0; mt < 2; mt++)
            #pragma unroll
            for (int nt = 0; nt < 8; nt++)
                #pragma unroll
                for (int q = 0; q < 4; q++) acc[mt][nt][q] = 0.0f;
        MMA_TILE256(AhA, AlA, BhA, BlA, acc, rbw, ch, lane);

        #pragma unroll
        for (int mt = 0; mt < 2; mt++) {
            const int row0 = rb + rbw + mt * 16 + lr;
            #pragma unroll
            for (int nt = 0; nt < 8; nt++) {
                const int col = ch * 64 + nt * 8 + (lane & 3) * 2;
                float2 v0 = { acc[mt][nt][0], acc[mt][nt][1] };
                float2 v1 = { acc[mt][nt][2], acc[mt][nt][3] };
                *(float2*)(g_hw[t] + (size_t)row0 * H + col)       = v0;
                *(float2*)(g_hw[t] + (size_t)(row0 + 8) * H + col) = v1;
            }
        }
        __syncthreads();
    }
}

// ====== h1[d] += sum over ALL types of sum_e hw_t[col[e]] (warp per row) =====
__global__ void __launch_bounds__(256) k_h1add_all() {
    const int warp = threadIdx.x >> 5, lane = threadIdx.x & 31;
    const int d = blockIdx.x * 8 + warp;
    float4 acc = {0.0f, 0.0f, 0.0f, 0.0f};
    #pragma unroll 1
    for (int t = 0; t < T_TYPES; t++) {
        const int start = g_ptr[t][d], deg = g_deg[t][d];
        const float* hwt = g_hw[t];
        for (int e = 0; e < deg; e++) {
            const int s = g_col[t][start + e];
            const float4 w4 = ((const float4*)(hwt + (size_t)s * H))[lane];
            acc.x += w4.x; acc.y += w4.y; acc.z += w4.z; acc.w += w4.w;
        }
    }
    float4* p = (float4*)(g_h1 + (size_t)d * H) + lane;
    float4 cur = *p;
    cur.x += acc.x; cur.y += acc.y; cur.z += acc.z; cur.w += acc.w;
    *p = cur;
}

// ===== tail MLP via MMA: out = relu(relu(h1)@W2 + b2) @ W3 + b3 ==============
__global__ void __launch_bounds__(512, 1) k_mlp_mma(
    const float* __restrict__ W2, const float* __restrict__ b2,
    const float* __restrict__ W3, const float* __restrict__ b3,
    float* __restrict__ out) {
    extern __shared__ char dsraw[];
    __shared__ float s_w3[64], s_b2[64], s_out[256];
    const uint32_t raw  = smem_u32(dsraw);
    const uint32_t base = (raw + 1023u) & ~1023u;
    char* dsm = dsraw + (base - raw);
    const int tid = threadIdx.x, warp = tid >> 5, lane = tid & 31;

    char* Ahp = dsm;
    char* Alp = dsm + ATILE2;
    char* Bhp = dsm + 2 * ATILE2;
    char* Blp = Bhp + W2T;
    for (int i = tid; i < 64 * H; i += 512) {
        const int k = i >> 6, n = i & 63;
        const float w = W2[k * 64 + n];
        const __nv_bfloat16 h = __float2bfloat16(w);
        *(__nv_bfloat16*)(Bhp + n * SA + k * 2) = h;
        *(__nv_bfloat16*)(Blp + n * SA + k * 2) = __float2bfloat16(w - __bfloat162float(h));
    }
    if (tid < 64) { s_w3[tid] = W3[tid]; s_b2[tid] = b2[tid]; }
    const float b3v = __ldg(b3);
    __syncthreads();

    const uint32_t AhA = smem_u32(Ahp), AlA = smem_u32(Alp);
    const uint32_t BhA = smem_u32(Bhp), BlA = smem_u32(Blp);
    const int rbw = (warp & 7) * 32;
    const int ch  = warp >> 3;

    for (int tile = blockIdx.x; tile < NUM_TX / 256; tile += gridDim.x) {
        const int rb = tile * 256;
        if (tid < 256) s_out[tid] = 0.0f;
        {
            const int r = tid >> 1, hf = tid & 1;
            const float4* src = (const float4*)(g_h1 + (size_t)(rb + r) * H) + hf * 16;
            char* ah = Ahp + r * SA + hf * 128;
            char* al = Alp + r * SA + hf * 128;
            #pragma unroll
            for (int j = 0; j < 16; j++) {
                float4 v = __ldg(src + j);
                v.x = fmaxf(v.x, 0.0f); v.y = fmaxf(v.y, 0.0f);
                v.z = fmaxf(v.z, 0.0f); v.w = fmaxf(v.w, 0.0f);
                uint32_t hi[2], lo[2];
                split4(v, hi, lo);
                *(uint32_t*)(ah + j * 8)     = hi[0];
                *(uint32_t*)(ah + j * 8 + 4) = hi[1];
                *(uint32_t*)(al + j * 8)     = lo[0];
                *(uint32_t*)(al + j * 8 + 4) = lo[1];
            }
        }
        __syncthreads();

        float acc[2][4][4];
        #pragma unroll
        for (int mt = 0; mt < 2; mt++)
            #pragma unroll
            for (int nt = 0; nt < 4; nt++)
                #pragma unroll
                for (int q = 0; q < 4; q++) acc[mt][nt][q] = 0.0f;

        {
            const uint32_t arow = rbw + (lane & 15);
            const uint32_t aqof = (lane >> 4) * 16;
            const uint32_t brow = ch * 32 + ((lane >> 4) * 8) + (lane & 7);
            const uint32_t bqof = ((lane >> 3) & 1) * 16;
            #pragma unroll
            for (int ks = 0; ks < 8; ks++) {
                const uint32_t kb = ks * 32;
                uint32_t ah[2][4], al[2][4], bh_[2][4], bl_[2][4];
                #pragma unroll
                for (int mt = 0; mt < 2; mt++) {
                    const uint32_t ao = (arow + mt * 16) * SA + kb + aqof;
                    ldmx4(ah[mt], AhA + ao);
                    ldmx4(al[mt], AlA + ao);
                }
                #pragma unroll
                for (int np = 0; np < 2; np++) {
                    const uint32_t bo = (brow + np * 16) * SA + kb + bqof;
                    ldmx4(bh_[np], BhA + bo);
                    ldmx4(bl_[np], BlA + bo);
                }
                #pragma unroll
                for (int np = 0; np < 2; np++)
                    #pragma unroll
                    for (int sb = 0; sb < 2; sb++) {
                        const int nt = np * 2 + sb;
                        #pragma unroll
                        for (int mt = 0; mt < 2; mt++) {
                            mma_bf16(acc[mt][nt], ah[mt], bh_[np][sb*2], bh_[np][sb*2+1]);
                            mma_bf16(acc[mt][nt], al[mt], bh_[np][sb*2], bh_[np][sb*2+1]);
                            mma_bf16(acc[mt][nt], ah[mt], bl_[np][sb*2], bl_[np][sb*2+1]);
                        }
                    }
            }
        }

        #pragma unroll
        for (int mt = 0; mt < 2; mt++) {
            const int row0 = rbw + mt * 16 + (lane >> 2), row1 = row0 + 8;
            float p0 = 0.0f, p1 = 0.0f;
            #pragma unroll
            for (int nt = 0; nt < 4; nt++) {
                const int col = ch * 32 + nt * 8 + (lane & 3) * 2;
                p0 += fmaxf(acc[mt][nt][0] + s_b2[col],     0.0f) * s_w3[col]
                    + fmaxf(acc[mt][nt][1] + s_b2[col + 1], 0.0f) * s_w3[col + 1];
                p1 += fmaxf(acc[mt][nt][2] + s_b2[col],     0.0f) * s_w3[col]
                    + fmaxf(acc[mt][nt][3] + s_b2[col + 1], 0.0f) * s_w3[col + 1];
            }
            #pragma unroll
            for (int o = 1; o < 4; o <<= 1) {
                p0 += __shfl_xor_sync(0xffffffffu, p0, o);
                p1 += __shfl_xor_sync(0xffffffffu, p1, o);
            }
            if ((lane & 3) == 0) {
                atomicAdd(&s_out[row0], p0);
                atomicAdd(&s_out[row1], p1);
            }
        }
        __syncthreads();
        if (tid < 256) out[rb + tid] = s_out[tid] + b3v;
        __syncthreads();
    }
}

// ================= host launcher =============================================
extern "C" void kernel_launch(void* const* d_in, const int* in_sizes, int n_in,
                              void* d_out, int out_size) {
    const float* tx_x = (const float*)d_in[0];
    const float* emb  = (const float*)d_in[1];
    const int*   eidx = (const int*)  d_in[2];
    const int*   esrc = (const int*)  d_in[3];
    const int*   edst = (const int*)  d_in[4];
    const float* Wq = (const float*)d_in[5],  *bq = (const float*)d_in[6];
    const float* Wk = (const float*)d_in[7];
    const float* Wv = (const float*)d_in[9],  *bv = (const float*)d_in[10];
    const float* Ws = (const float*)d_in[11], *bs = (const float*)d_in[12];
    const float* lns = (const float*)d_in[13], *lnb = (const float*)d_in[14];
    const float* W1 = (const float*)d_in[15], *b1 = (const float*)d_in[16];
    const float* W2 = (const float*)d_in[17], *b2 = (const float*)d_in[18];
    const float* W3 = (const float*)d_in[19], *b3 = (const float*)d_in[20];
    float* out = (float*)d_out;

    const int SM256    = 2 * ATILE2 + 2 * BTILE + 1024;  // 209920
    const int MLP_SMEM = 2 * ATILE2 + 2 * W2T + 1024;    // 175104
    cudaFuncSetAttribute(k_init_mma, cudaFuncAttributeMaxDynamicSharedMemorySize, SM256);
    cudaFuncSetAttribute(k_z_mma,    cudaFuncAttributeMaxDynamicSharedMemorySize, SM256);
    cudaFuncSetAttribute(k_fused,    cudaFuncAttributeMaxDynamicSharedMemorySize, SM256);
    cudaFuncSetAttribute(k_mlp_mma,  cudaFuncAttributeMaxDynamicSharedMemorySize, MLP_SMEM);

    k_prep <<<128, 128>>>(Wq, Wk, bq);
    k_mkimg<<<2 + T_TYPES, 256>>>(Wv, Ws, W1);

    k_zero_deg<<<(T_TYPES * N_ENT + 255) / 256, 256>>>();
    k_count   <<<(T_TYPES * NE + 255) / 256, 256>>>(edst);
    k_scan    <<<T_TYPES, 1024>>>();
    k_fill    <<<(T_TYPES * NE + 255) / 256, 256>>>(esrc, edst);

    k_init_mma<<<148, 512, SM256>>>(tx_x, W1, b1);

    k_z_mma  <<<148, 512, SM256>>>(emb, eidx);
    k_attn   <<<T_TYPES * (N_ENT / 8), 256>>>();
    k_fused  <<<148, 512, SM256>>>(bv, bs, lns, lnb);
    k_h1add_all<<<NUM_TX / 8, 256>>>();

    k_mlp_mma<<<148, 512, MLP_SMEM>>>(W2, b2, W3, b3, out);
}

// round 14
// speedup vs baseline: 1.0913x; 1.0913x over previous
#include <cuda_runtime.h>
#include <cuda_bf16.h>
#include <math.h>
#include <stdint.h>

#define T_TYPES 11
#define NUM_TX  131072
#define N_ENT   131072
#define NE      262144
#define H       128
#define TXF     394
#define LN_EPS  1e-5f
#define INV_SQRT_D 0.08838834764831845f   // 1/sqrt(128)

// bf16 tile strides (bytes): 128 bf16 = 256B + 16B pad -> conflict-free ldmatrix
#define SA 272
#define ATILE2  69632     // 256 rows * 272B
#define BTILE   34816     // 128 n-rows * 272B
#define W2T     17408     // 64 n-rows * 272B

// ---------------- scratch (device globals; no cudaMalloc allowed) ----------
__device__ uint32_t g_zb [T_TYPES][(size_t)N_ENT * 64];  // bf16x2 z rows
__device__ float g_x   [T_TYPES][(size_t)N_ENT * H];
__device__ float g_xagg[T_TYPES][(size_t)N_ENT * H];
__device__ float g_hw  [T_TYPES][(size_t)N_ENT * H];
__device__ float g_c   [T_TYPES][N_ENT];
__device__ float g_h1  [(size_t)NUM_TX * H];
__device__ float g_weff[H * H];               // Wz[k][n]
__device__ float g_wkbq[H];

// precomputed split-bf16 swizzled B images: [hi BTILE][lo BTILE]
__device__ uint4 g_img_v [(2 * BTILE) / 16];
__device__ uint4 g_img_s [(2 * BTILE) / 16];
__device__ uint4 g_img_w1[T_TYPES][(2 * BTILE) / 16];

// CSR over dst, per type
__device__ int g_deg [T_TYPES][N_ENT];
__device__ int g_ptr [T_TYPES][N_ENT];
__device__ int g_cur [T_TYPES][N_ENT];
__device__ int g_col [T_TYPES][NE];
__device__ int g_bsum[T_TYPES][64];

// ================= helpers ===================================================
__device__ __forceinline__ uint32_t smem_u32(const void* p) {
    uint32_t a;
    asm("{ .reg .u64 t; cvta.to.shared.u64 t, %1; cvt.u32.u64 %0, t; }" : "=r"(a) : "l"(p));
    return a;
}
__device__ __forceinline__ void ldmx4(uint32_t* r, uint32_t addr) {
    asm volatile("ldmatrix.sync.aligned.m8n8.x4.shared.b16 {%0,%1,%2,%3}, [%4];"
        : "=r"(r[0]), "=r"(r[1]), "=r"(r[2]), "=r"(r[3]) : "r"(addr));
}
__device__ __forceinline__ void mma_bf16(float* c, const uint32_t* a, uint32_t b0, uint32_t b1) {
    asm volatile("mma.sync.aligned.m16n8k16.row.col.f32.bf16.bf16.f32 "
        "{%0,%1,%2,%3}, {%4,%5,%6,%7}, {%8,%9}, {%0,%1,%2,%3};"
        : "+f"(c[0]), "+f"(c[1]), "+f"(c[2]), "+f"(c[3])
        : "r"(a[0]), "r"(a[1]), "r"(a[2]), "r"(a[3]), "r"(b0), "r"(b1));
}
__device__ __forceinline__ uint32_t bfpack(float a, float b) {
    __nv_bfloat162 t = __floats2bfloat162_rn(a, b);
    return reinterpret_cast<uint32_t&>(t);
}
__device__ __forceinline__ void split4(float4 v, uint32_t* hi, uint32_t* lo) {
    __nv_bfloat16 hx = __float2bfloat16(v.x), hy = __float2bfloat16(v.y);
    __nv_bfloat16 hz = __float2bfloat16(v.z), hw = __float2bfloat16(v.w);
    __nv_bfloat162 h01; h01.x = hx; h01.y = hy;
    __nv_bfloat162 h23; h23.x = hz; h23.y = hw;
    hi[0] = reinterpret_cast<uint32_t&>(h01);
    hi[1] = reinterpret_cast<uint32_t&>(h23);
    lo[0] = bfpack(v.x - __bfloat162float(hx), v.y - __bfloat162float(hy));
    lo[1] = bfpack(v.z - __bfloat162float(hz), v.w - __bfloat162float(hw));
}
__device__ __forceinline__ void split2(float a, float b, uint32_t& hi, uint32_t& lo) {
    __nv_bfloat16 ha = __float2bfloat16(a), hb = __float2bfloat16(b);
    __nv_bfloat162 hp; hp.x = ha; hp.y = hb;
    hi = reinterpret_cast<uint32_t&>(hp);
    lo = bfpack(a - __bfloat162float(ha), b - __bfloat162float(hb));
}
__device__ __forceinline__ void conv_B(const float* __restrict__ W, char* bh, char* bl,
                                       int tid, int nthr) {
    for (int i = tid; i < H * H; i += nthr) {
        const int k = i >> 7, n = i & 127;
        const float w = W[i];
        const __nv_bfloat16 h = __float2bfloat16(w);
        *(__nv_bfloat16*)(bh + n * SA + k * 2) = h;
        *(__nv_bfloat16*)(bl + n * SA + k * 2) = __float2bfloat16(w - __bfloat162float(h));
    }
}
__device__ __forceinline__ void copy_img(const uint4* __restrict__ img, char* bh, int tid) {
    uint4* d = (uint4*)bh;
    for (int i = tid; i < (2 * BTILE) / 16; i += 512) d[i] = __ldg(img + i);
}

// ================= prep: Wz = Wk Wq^T, wkbq = Wk bq ==========================
__global__ void k_prep(const float* __restrict__ Wq, const float* __restrict__ Wk,
                       const float* __restrict__ bq) {
    __shared__ float wkrow[H];
    const int b = blockIdx.x, a = threadIdx.x;
    wkrow[a] = Wk[b * H + a];
    __syncthreads();
    float s = 0.0f;
    #pragma unroll 4
    for (int j = 0; j < H; j++) s = fmaf(wkrow[j], Wq[a * H + j], s);
    g_weff[b * H + a] = s;
    if (b == 0) {
        float t = 0.0f;
        for (int j = 0; j < H; j++) t = fmaf(Wk[a * H + j], bq[j], t);
        g_wkbq[a] = t;
    }
}

// ================= build split-bf16 B images =================================
__global__ void k_mkimg(const float* __restrict__ Wv, const float* __restrict__ Ws,
                        const float* __restrict__ W1) {
    const int b = blockIdx.x;
    const float* W;
    uint8_t* img;
    if (b == 0)      { W = Wv; img = (uint8_t*)g_img_v; }
    else if (b == 1) { W = Ws; img = (uint8_t*)g_img_s; }
    else             { W = W1 + (size_t)(TXF + (b - 2) * H) * H;
                       img = (uint8_t*)g_img_w1[b - 2]; }
    for (int i = threadIdx.x; i < H * H; i += 256) {
        const int k = i >> 7, n = i & 127;
        const float w = W[i];
        const __nv_bfloat16 h = __float2bfloat16(w);
        *(__nv_bfloat16*)(img + n * SA + k * 2) = h;
        *(__nv_bfloat16*)(img + BTILE + n * SA + k * 2) =
            __float2bfloat16(w - __bfloat162float(h));
    }
}

// ================= CSR build =================================================
__global__ void k_zero_deg() {
    const int i = blockIdx.x * blockDim.x + threadIdx.x;
    if (i < T_TYPES * N_ENT) ((int*)g_deg)[i] = 0;
}
__global__ void k_count(const int* __restrict__ edst) {
    const int i = blockIdx.x * blockDim.x + threadIdx.x;
    if (i >= T_TYPES * NE) return;
    const int t = i / NE;
    atomicAdd(&g_deg[t][edst[i]], 1);
}
__global__ void k_scanA() {
    const int t = blockIdx.x >> 6, c = blockIdx.x & 63;
    const int base = c * 2048, tid = threadIdx.x;
    int v[8], s = 0;
    #pragma unroll
    for (int j = 0; j < 8; j++) { v[j] = g_deg[t][base + tid * 8 + j]; s += v[j]; }
    __shared__ int sm[256];
    sm[tid] = s; __syncthreads();
    for (int off = 1; off < 256; off <<= 1) {
        int x = (tid >= off) ? sm[tid - off] : 0;
        __syncthreads();
        sm[tid] += x;
        __syncthreads();
    }
    int run = (tid == 0) ? 0 : sm[tid - 1];
    if (tid == 255) g_bsum[t][c] = sm[255];
    #pragma unroll
    for (int j = 0; j < 8; j++) { g_ptr[t][base + tid * 8 + j] = run; run += v[j]; }
}
__global__ void k_scanB() {
    const int t = blockIdx.x, tid = threadIdx.x;
    __shared__ int sm[64];
    sm[tid] = g_bsum[t][tid]; __syncthreads();
    for (int off = 1; off < 64; off <<= 1) {
        int x = (tid >= off) ? sm[tid - off] : 0;
        __syncthreads();
        sm[tid] += x;
        __syncthreads();
    }
    g_bsum[t][tid] = (tid == 0) ? 0 : sm[tid - 1];
}
__global__ void k_scanC() {
    const int t = blockIdx.x >> 6, c = blockIdx.x & 63;
    const int base = c * 2048, tid = threadIdx.x;
    const int add = g_bsum[t][c];
    #pragma unroll
    for (int j = 0; j < 8; j++) {
        const int i = base + tid * 8 + j;
        const int p = g_ptr[t][i] + add;
        g_ptr[t][i] = p;
        g_cur[t][i] = p;
    }
}
__global__ void k_fill(const int* __restrict__ esrc, const int* __restrict__ edst) {
    const int i = blockIdx.x * blockDim.x + threadIdx.x;
    if (i >= T_TYPES * NE) return;
    const int t = i / NE;
    const int slot = atomicAdd(&g_cur[t][edst[i]], 1);
    g_col[t][slot] = esrc[i];
}

// ================= MMA core (256-row tile, acc[2][8][4], 16 warps) ==========
#define MMA_TILE256(AhA, AlA, BhA, BlA, acc, rbw, ch, lane)                          \
    {                                                                                 \
        const uint32_t arow = (rbw) + ((lane) & 15);                                  \
        const uint32_t aqof = ((lane) >> 4) * 16;                                     \
        const uint32_t brow = (ch) * 64 + (((lane) >> 4) * 8) + ((lane) & 7);         \
        const uint32_t bqof = (((lane) >> 3) & 1) * 16;                               \
        _Pragma("unroll")                                                             \
        for (int ks = 0; ks < 8; ks++) {                                              \
            const uint32_t kb = ks * 32;                                              \
            uint32_t ah[2][4], al[2][4], bf[4][4];                                    \
            _Pragma("unroll")                                                         \
            for (int mt = 0; mt < 2; mt++) {                                          \
                const uint32_t ao = (arow + mt * 16) * SA + kb + aqof;                \
                ldmx4(ah[mt], (AhA) + ao);                                            \
                ldmx4(al[mt], (AlA) + ao);                                            \
            }                                                                         \
            _Pragma("unroll")                                                         \
            for (int np = 0; np < 4; np++)                                            \
                ldmx4(bf[np], (BhA) + (brow + np * 16) * SA + kb + bqof);             \
            _Pragma("unroll")                                                         \
            for (int np = 0; np < 4; np++)                                            \
                _Pragma("unroll")                                                     \
                for (int sb = 0; sb < 2; sb++) {                                      \
                    const int nt = np * 2 + sb;                                       \
                    _Pragma("unroll")                                                 \
                    for (int mt = 0; mt < 2; mt++) {                                  \
                        mma_bf16(acc[mt][nt], ah[mt], bf[np][sb*2], bf[np][sb*2+1]);  \
                        mma_bf16(acc[mt][nt], al[mt], bf[np][sb*2], bf[np][sb*2+1]);  \
                    }                                                                 \
                }                                                                     \
            _Pragma("unroll")                                                         \
            for (int np = 0; np < 4; np++)                                            \
                ldmx4(bf[np], (BlA) + (brow + np * 16) * SA + kb + bqof);             \
            _Pragma("unroll")                                                         \
            for (int np = 0; np < 4; np++)                                            \
                _Pragma("unroll")                                                     \
                for (int sb = 0; sb < 2; sb++) {                                      \
                    const int nt = np * 2 + sb;                                       \
                    _Pragma("unroll")                                                 \
                    for (int mt = 0; mt < 2; mt++)                                    \
                        mma_bf16(acc[mt][nt], ah[mt], bf[np][sb*2], bf[np][sb*2+1]);  \
                }                                                                     \
        }                                                                             \
    }

// ================= init_h1 via MMA: b1 + tx_x @ W1[0:394] ====================
__global__ void __launch_bounds__(512, 1) k_init_mma(const float* __restrict__ tx,
                                                     const float* __restrict__ W1,
                                                     const float* __restrict__ b1) {
    extern __shared__ char dsraw[];
    __shared__ float s_b1[H];
    const uint32_t raw  = smem_u32(dsraw);
    const uint32_t base = (raw + 1023u) & ~1023u;
    char* dsm = dsraw + (base - raw);
    const int tid = threadIdx.x, warp = tid >> 5, lane = tid & 31;

    char* Ahp = dsm;
    char* Alp = dsm + ATILE2;
    char* Bhp = dsm + 2 * ATILE2;
    char* Blp = Bhp + BTILE;
    const uint32_t AhA = smem_u32(Ahp), AlA = smem_u32(Alp);
    const uint32_t BhA = smem_u32(Bhp), BlA = smem_u32(Blp);

    if (tid < H) s_b1[tid] = b1[tid];

    const int rbw = (warp & 7) * 32;
    const int ch  = warp >> 3;

    for (int tile = blockIdx.x; tile < NUM_TX / 256; tile += gridDim.x) {
        const int rb = tile * 256;
        float acc[2][8][4];
        #pragma unroll
        for (int mt = 0; mt < 2; mt++)
            #pragma unroll
            for (int nt = 0; nt < 8; nt++)
                #pragma unroll
                for (int q = 0; q < 4; q++) acc[mt][nt][q] = 0.0f;

        for (int chunk = 0; chunk < 4; chunk++) {
            __syncthreads();
            const int kcols = (chunk < 3) ? 128 : 16;
            for (int i = tid; i < kcols * H; i += 512) {
                const int k = i >> 7, n = i & 127;
                const int kk = chunk * 128 + k;
                const float w = (kk < TXF) ? W1[(size_t)kk * H + n] : 0.0f;
                const __nv_bfloat16 h = __float2bfloat16(w);
                *(__nv_bfloat16*)(Bhp + n * SA + k * 2) = h;
                *(__nv_bfloat16*)(Blp + n * SA + k * 2) =
                    __float2bfloat16(w - __bfloat162float(h));
            }
            const int r = tid >> 1, hf = tid & 1;
            const float* rowp = tx + (size_t)(rb + r) * TXF;
            if (chunk < 3) {
                const float2* src = (const float2*)(rowp + chunk * 128 + hf * 64);
                char* ah = Ahp + r * SA + hf * 128;
                char* al = Alp + r * SA + hf * 128;
                #pragma unroll
                for (int j = 0; j < 16; j++) {
                    const float2 a = __ldg(src + j * 2);
                    const float2 b = __ldg(src + j * 2 + 1);
                    float4 v = { a.x, a.y, b.x, b.y };
                    uint32_t hi[2], lo[2];
                    split4(v, hi, lo);
                    *(uint32_t*)(ah + j * 8)     = hi[0];
                    *(uint32_t*)(ah + j * 8 + 4) = hi[1];
                    *(uint32_t*)(al + j * 8)     = lo[0];
                    *(uint32_t*)(al + j * 8 + 4) = lo[1];
                }
            } else {
                float vals[8];
                #pragma unroll
                for (int j = 0; j < 8; j++) {
                    const int c = 384 + hf * 8 + j;
                    vals[j] = (c < TXF) ? __ldg(rowp + c) : 0.0f;
                }
                char* ah = Ahp + r * SA + hf * 16;
                char* al = Alp + r * SA + hf * 16;
                #pragma unroll
                for (int p = 0; p < 4; p++) {
                    float4 v = { vals[p*2], vals[p*2+1], 0.0f, 0.0f };
                    uint32_t hi[2], lo[2];
                    split4(v, hi, lo);
                    *(uint32_t*)(ah + p * 4) = hi[0];
                    *(uint32_t*)(al + p * 4) = lo[0];
                }
            }
            __syncthreads();

            const uint32_t arow = rbw + (lane & 15);
            const uint32_t aqof = (lane >> 4) * 16;
            const uint32_t brow = ch * 64 + ((lane >> 4) * 8) + (lane & 7);
            const uint32_t bqof = ((lane >> 3) & 1) * 16;
            const int nks = (chunk < 3) ? 8 : 1;
            for (int ks = 0; ks < nks; ks++) {
                const uint32_t kb = ks * 32;
                uint32_t ah[2][4], al[2][4], bf[4][4];
                #pragma unroll
                for (int mt = 0; mt < 2; mt++) {
                    const uint32_t ao = (arow + mt * 16) * SA + kb + aqof;
                    ldmx4(ah[mt], AhA + ao);
                    ldmx4(al[mt], AlA + ao);
                }
                #pragma unroll
                for (int np = 0; np < 4; np++)
                    ldmx4(bf[np], BhA + (brow + np * 16) * SA + kb + bqof);
                #pragma unroll
                for (int np = 0; np < 4; np++)
                    #pragma unroll
                    for (int sb = 0; sb < 2; sb++) {
                        const int nt = np * 2 + sb;
                        #pragma unroll
                        for (int mt = 0; mt < 2; mt++) {
                            mma_bf16(acc[mt][nt], ah[mt], bf[np][sb*2], bf[np][sb*2+1]);
                            mma_bf16(acc[mt][nt], al[mt], bf[np][sb*2], bf[np][sb*2+1]);
                        }
                    }
                #pragma unroll
                for (int np = 0; np < 4; np++)
                    ldmx4(bf[np], BlA + (brow + np * 16) * SA + kb + bqof);
                #pragma unroll
                for (int np = 0; np < 4; np++)
                    #pragma unroll
                    for (int sb = 0; sb < 2; sb++) {
                        const int nt = np * 2 + sb;
                        #pragma unroll
                        for (int mt = 0; mt < 2; mt++)
                            mma_bf16(acc[mt][nt], ah[mt], bf[np][sb*2], bf[np][sb*2+1]);
                    }
            }
        }
        #pragma unroll
        for (int mt = 0; mt < 2; mt++) {
            const int row0 = rb + rbw + mt * 16 + (lane >> 2);
            #pragma unroll
            for (int nt = 0; nt < 8; nt++) {
                const int col = ch * 64 + nt * 8 + (lane & 3) * 2;
                const float b0 = s_b1[col], b1v = s_b1[col + 1];
                float2 v0 = { acc[mt][nt][0] + b0, acc[mt][nt][1] + b1v };
                float2 v1 = { acc[mt][nt][2] + b0, acc[mt][nt][3] + b1v };
                *(float2*)(g_h1 + (size_t)row0 * H + col)       = v0;
                *(float2*)(g_h1 + (size_t)(row0 + 8) * H + col) = v1;
            }
        }
    }
}

// ====== Z GEMM (ALL types): gather x, zb = bf16(x@Wz), c = x.wkbq ============
__global__ void __launch_bounds__(512, 1) k_z_mma(const float* __restrict__ emb,
                                                  const int* __restrict__ idx) {
    extern __shared__ char dsraw[];
    __shared__ float s_wkbq[H];
    const uint32_t raw  = smem_u32(dsraw);
    const uint32_t base = (raw + 1023u) & ~1023u;
    char* dsm = dsraw + (base - raw);
    const int tid = threadIdx.x, warp = tid >> 5, lane = tid & 31;

    char* Ahp = dsm;
    char* Alp = dsm + ATILE2;
    char* Bhp = dsm + 2 * ATILE2;
    char* Blp = Bhp + BTILE;
    conv_B(g_weff, Bhp, Blp, tid, 512);
    if (tid < H) s_wkbq[tid] = g_wkbq[tid];
    __syncthreads();

    const uint32_t AhA = smem_u32(Ahp), AlA = smem_u32(Alp);
    const uint32_t BhA = smem_u32(Bhp), BlA = smem_u32(Blp);
    const int rbw = (warp & 7) * 32;
    const int ch  = warp >> 3;

    for (int tile = blockIdx.x; tile < T_TYPES * (N_ENT / 256); tile += gridDim.x) {
        const int t  = tile >> 9;                 // 512 tiles per type
        const int rb = (tile & 511) * 256;
        const float* embt = emb + (size_t)t * N_ENT * H;
        const int*   idxt = idx + (size_t)t * N_ENT;
        {
            const int r = tid >> 1, hf = tid & 1;
            const int e = __ldg(idxt + rb + r);
            const float4* src = (const float4*)(embt + (size_t)e * H) + hf * 16;
            float4* xdst = (float4*)(g_x[t] + (size_t)(rb + r) * H) + hf * 16;
            char* ah = Ahp + r * SA + hf * 128;
            char* al = Alp + r * SA + hf * 128;
            float cp = 0.0f;
            #pragma unroll
            for (int j = 0; j < 16; j++) {
                const float4 v = __ldg(src + j);
                uint32_t hi[2], lo[2];
                split4(v, hi, lo);
                *(uint32_t*)(ah + j * 8)     = hi[0];
                *(uint32_t*)(ah + j * 8 + 4) = hi[1];
                *(uint32_t*)(al + j * 8)     = lo[0];
                *(uint32_t*)(al + j * 8 + 4) = lo[1];
                xdst[j] = v;
                const float* wb = s_wkbq + hf * 64 + j * 4;
                cp += v.x * wb[0] + v.y * wb[1] + v.z * wb[2] + v.w * wb[3];
            }
            cp += __shfl_xor_sync(0xffffffffu, cp, 1);
            if (hf == 0) g_c[t][rb + r] = cp;
        }
        __syncthreads();

        float acc[2][8][4];
        #pragma unroll
        for (int mt = 0; mt < 2; mt++)
            #pragma unroll
            for (int nt = 0; nt < 8; nt++)
                #pragma unroll
                for (int q = 0; q < 4; q++) acc[mt][nt][q] = 0.0f;

        MMA_TILE256(AhA, AlA, BhA, BlA, acc, rbw, ch, lane);

        #pragma unroll
        for (int mt = 0; mt < 2; mt++) {
            const int row0 = rb + rbw + mt * 16 + (lane >> 2);
            #pragma unroll
            for (int nt = 0; nt < 8; nt++) {
                const int col = ch * 64 + nt * 8 + (lane & 3) * 2;
                g_zb[t][(size_t)row0 * 64 + (col >> 1)] =
                    bfpack(acc[mt][nt][0], acc[mt][nt][1]);
                g_zb[t][(size_t)(row0 + 8) * 64 + (col >> 1)] =
                    bfpack(acc[mt][nt][2], acc[mt][nt][3]);
            }
        }
        __syncthreads();
    }
}

// ================= attention aggregation (ALL types; warp per dst) ===========
__global__ void __launch_bounds__(256) k_attn() {
    const int warp = threadIdx.x >> 5, lane = threadIdx.x & 31;
    const int t = blockIdx.x >> 14;               // 16384 blocks per type
    const int d = (blockIdx.x & 16383) * 8 + warp;
    const float4 xd4 = ((const float4*)(g_x[t] + (size_t)d * H))[lane];
    const int start = g_ptr[t][d], deg = g_deg[t][d];

    float den = 0.0f;
    float4 acc = {0.0f, 0.0f, 0.0f, 0.0f};
    int s_next = (deg > 0) ? __ldg(&g_col[t][start]) : 0;
    for (int e = 0; e < deg; e++) {
        const int s = s_next;
        if (e + 1 < deg) s_next = __ldg(&g_col[t][start + e + 1]);
        const uint2 z2 = *((const uint2*)(g_zb[t] + (size_t)s * 64) + lane);
        const float2 z0 = __bfloat1622float2(*(const __nv_bfloat162*)&z2.x);
        const float2 z1 = __bfloat1622float2(*(const __nv_bfloat162*)&z2.y);
        const float4 x4 = ((const float4*)(g_x[t] + (size_t)s * H))[lane];
        float dot = xd4.x * z0.x + xd4.y * z0.y + xd4.z * z1.x + xd4.w * z1.y;
        #pragma unroll
        for (int o = 16; o; o >>= 1) dot += __shfl_xor_sync(0xffffffffu, dot, o);
        const float w = expf((dot + __ldg(&g_c[t][s])) * INV_SQRT_D);
        den += w;
        acc.x += w * x4.x; acc.y += w * x4.y; acc.z += w * x4.z; acc.w += w * x4.w;
    }
    const float inv = (deg > 0) ? 1.0f / den : 0.0f;
    float4 o4 = { acc.x * inv, acc.y * inv, acc.z * inv, acc.w * inv };
    ((float4*)(g_xagg[t] + (size_t)d * H))[lane] = o4;
}

// ===== fused (ALL types): h = LN(xagg@Wv + x@Ws + bv+bs)*g+b; hw = h@W1_t ====
__global__ void __launch_bounds__(512, 1) k_fused(
    const float* __restrict__ bv, const float* __restrict__ bs,
    const float* __restrict__ lns, const float* __restrict__ lnb) {
    extern __shared__ char dsraw[];
    __shared__ float s_bias[H], s_g[H], s_b[H];
    __shared__ float sS1[256], sS2[256], sMu[256], sRstd[256];
    const uint32_t raw  = smem_u32(dsraw);
    const uint32_t base = (raw + 1023u) & ~1023u;
    char* dsm = dsraw + (base - raw);
    const int tid = threadIdx.x, warp = tid >> 5, lane = tid & 31;

    char* Ahp = dsm;
    char* Alp = dsm + ATILE2;
    char* Bhp = dsm + 2 * ATILE2;
    const uint32_t AhA = smem_u32(Ahp), AlA = smem_u32(Alp);
    const uint32_t BhA = smem_u32(Bhp), BlA = BhA + BTILE;
    const int rbw = (warp & 7) * 32;
    const int ch  = warp >> 3;

    for (int tile = blockIdx.x; tile < T_TYPES * (N_ENT / 256); tile += gridDim.x) {
        const int t  = tile >> 9;
        const int rb = (tile & 511) * 256;
        float acc[2][8][4];
        #pragma unroll
        for (int mt = 0; mt < 2; mt++)
            #pragma unroll
            for (int nt = 0; nt < 8; nt++)
                #pragma unroll
                for (int q = 0; q < 4; q++) acc[mt][nt][q] = 0.0f;

        // ---- stage 1: B <- Wv image, gather xagg, zero stats, LN params
        copy_img(g_img_v, Bhp, tid);
        {
            const int r = tid >> 1, hf = tid & 1;
            const float4* src = (const float4*)(g_xagg[t] + (size_t)(rb + r) * H) + hf * 16;
            char* ah = Ahp + r * SA + hf * 128;
            char* al = Alp + r * SA + hf * 128;
            #pragma unroll
            for (int j = 0; j < 16; j++) {
                uint32_t hi[2], lo[2];
                split4(__ldg(src + j), hi, lo);
                *(uint32_t*)(ah + j * 8)     = hi[0];
                *(uint32_t*)(ah + j * 8 + 4) = hi[1];
                *(uint32_t*)(al + j * 8)     = lo[0];
                *(uint32_t*)(al + j * 8 + 4) = lo[1];
            }
        }
        if (tid < 256) { sS1[tid] = 0.0f; sS2[tid] = 0.0f; }
        if (tid < H) {
            s_bias[tid] = __ldg(bv + tid) + __ldg(bs + tid);
            s_g[tid] = __ldg(lns + t * H + tid);
            s_b[tid] = __ldg(lnb + t * H + tid);
        }
        __syncthreads();
        MMA_TILE256(AhA, AlA, BhA, BlA, acc, rbw, ch, lane);
        __syncthreads();

        // ---- stage 2: B <- Ws image, gather x
        copy_img(g_img_s, Bhp, tid);
        {
            const int r = tid >> 1, hf = tid & 1;
            const float4* src = (const float4*)(g_x[t] + (size_t)(rb + r) * H) + hf * 16;
            char* ah = Ahp + r * SA + hf * 128;
            char* al = Alp + r * SA + hf * 128;
            #pragma unroll
            for (int j = 0; j < 16; j++) {
                uint32_t hi[2], lo[2];
                split4(__ldg(src + j), hi, lo);
                *(uint32_t*)(ah + j * 8)     = hi[0];
                *(uint32_t*)(ah + j * 8 + 4) = hi[1];
                *(uint32_t*)(al + j * 8)     = lo[0];
                *(uint32_t*)(al + j * 8 + 4) = lo[1];
            }
        }
        __syncthreads();
        MMA_TILE256(AhA, AlA, BhA, BlA, acc, rbw, ch, lane);

        // ---- bias + LN stats over 256 local rows
        const int lr = lane >> 2;
        #pragma unroll
        for (int mt = 0; mt < 2; mt++) {
            const int row0 = rbw + mt * 16 + lr, row1 = row0 + 8;
            float s1a = 0, s2a = 0, s1b = 0, s2b = 0;
            #pragma unroll
            for (int nt = 0; nt < 8; nt++) {
                const int col = ch * 64 + nt * 8 + (lane & 3) * 2;
                acc[mt][nt][0] += s_bias[col]; acc[mt][nt][1] += s_bias[col + 1];
                acc[mt][nt][2] += s_bias[col]; acc[mt][nt][3] += s_bias[col + 1];
                s1a += acc[mt][nt][0] + acc[mt][nt][1];
                s2a += acc[mt][nt][0] * acc[mt][nt][0] + acc[mt][nt][1] * acc[mt][nt][1];
                s1b += acc[mt][nt][2] + acc[mt][nt][3];
                s2b += acc[mt][nt][2] * acc[mt][nt][2] + acc[mt][nt][3] * acc[mt][nt][3];
            }
            #pragma unroll
            for (int o = 1; o < 4; o <<= 1) {
                s1a += __shfl_xor_sync(0xffffffffu, s1a, o);
                s2a += __shfl_xor_sync(0xffffffffu, s2a, o);
                s1b += __shfl_xor_sync(0xffffffffu, s1b, o);
                s2b += __shfl_xor_sync(0xffffffffu, s2b, o);
            }
            if ((lane & 3) == 0) {
                atomicAdd(&sS1[row0], s1a); atomicAdd(&sS2[row0], s2a);
                atomicAdd(&sS1[row1], s1b); atomicAdd(&sS2[row1], s2b);
            }
        }
        __syncthreads();
        if (tid < 256) {
            const float mu = sS1[tid] * (1.0f / H);
            const float var = sS2[tid] * (1.0f / H) - mu * mu;
            sMu[tid] = mu;
            sRstd[tid] = rsqrtf(var + LN_EPS);
        }
        __syncthreads();

        // ---- stage 3: h -> A tile (split bf16), B <- W1t image
        #pragma unroll
        for (int mt = 0; mt < 2; mt++) {
            const int row0 = rbw + mt * 16 + lr, row1 = row0 + 8;
            const float mu0 = sMu[row0], rs0 = sRstd[row0];
            const float mu1 = sMu[row1], rs1 = sRstd[row1];
            #pragma unroll
            for (int nt = 0; nt < 8; nt++) {
                const int col = ch * 64 + nt * 8 + (lane & 3) * 2;
                const float g0 = s_g[col], g1 = s_g[col + 1];
                const float b0 = s_b[col], b1v = s_b[col + 1];
                const float h00 = (acc[mt][nt][0] - mu0) * rs0 * g0 + b0;
                const float h01 = (acc[mt][nt][1] - mu0) * rs0 * g1 + b1v;
                const float h10 = (acc[mt][nt][2] - mu1) * rs1 * g0 + b0;
                const float h11 = (acc[mt][nt][3] - mu1) * rs1 * g1 + b1v;
                uint32_t hi, lo;
                split2(h00, h01, hi, lo);
                *(uint32_t*)(Ahp + row0 * SA + col * 2) = hi;
                *(uint32_t*)(Alp + row0 * SA + col * 2) = lo;
                split2(h10, h11, hi, lo);
                *(uint32_t*)(Ahp + row1 * SA + col * 2) = hi;
                *(uint32_t*)(Alp + row1 * SA + col * 2) = lo;
            }
        }
        copy_img(g_img_w1[t], Bhp, tid);
        __syncthreads();

        // ---- stage 3 GEMM: hw = h @ W1t
        #pragma unroll
        for (int mt = 0; mt < 2; mt++)
            #pragma unroll
            for (int nt = 0; nt < 8; nt++)
                #pragma unroll
                for (int q = 0; q < 4; q++) acc[mt][nt][q] = 0.0f;
        MMA_TILE256(AhA, AlA, BhA, BlA, acc, rbw, ch, lane);

        #pragma unroll
        for (int mt = 0; mt < 2; mt++) {
            const int row0 = rb + rbw + mt * 16 + lr;
            #pragma unroll
            for (int nt = 0; nt < 8; nt++) {
                const int col = ch * 64 + nt * 8 + (lane & 3) * 2;
                float2 v0 = { acc[mt][nt][0], acc[mt][nt][1] };
                float2 v1 = { acc[mt][nt][2], acc[mt][nt][3] };
                *(float2*)(g_hw[t] + (size_t)row0 * H + col)       = v0;
                *(float2*)(g_hw[t] + (size_t)(row0 + 8) * H + col) = v1;
            }
        }
        __syncthreads();
    }
}

// ====== h1[d] += sum over ALL types of sum_e hw_t[col[e]] (warp per row) =====
__global__ void __launch_bounds__(256) k_h1add_all() {
    const int warp = threadIdx.x >> 5, lane = threadIdx.x & 31;
    const int d = blockIdx.x * 8 + warp;
    float4 acc = {0.0f, 0.0f, 0.0f, 0.0f};
    #pragma unroll 1
    for (int t = 0; t < T_TYPES; t++) {
        const int start = g_ptr[t][d], deg = g_deg[t][d];
        const float* hwt = g_hw[t];
        for (int e = 0; e < deg; e++) {
            const int s = g_col[t][start + e];
            const float4 w4 = ((const float4*)(hwt + (size_t)s * H))[lane];
            acc.x += w4.x; acc.y += w4.y; acc.z += w4.z; acc.w += w4.w;
        }
    }
    float4* p = (float4*)(g_h1 + (size_t)d * H) + lane;
    float4 cur = *p;
    cur.x += acc.x; cur.y += acc.y; cur.z += acc.z; cur.w += acc.w;
    *p = cur;
}

// ===== tail MLP via MMA: out = relu(relu(h1)@W2 + b2) @ W3 + b3 ==============
__global__ void __launch_bounds__(512, 1) k_mlp_mma(
    const float* __restrict__ W2, const float* __restrict__ b2,
    const float* __restrict__ W3, const float* __restrict__ b3,
    float* __restrict__ out) {
    extern __shared__ char dsraw[];
    __shared__ float s_w3[64], s_b2[64], s_out[256];
    const uint32_t raw  = smem_u32(dsraw);
    const uint32_t base = (raw + 1023u) & ~1023u;
    char* dsm = dsraw + (base - raw);
    const int tid = threadIdx.x, warp = tid >> 5, lane = tid & 31;

    char* Ahp = dsm;
    char* Alp = dsm + ATILE2;
    char* Bhp = dsm + 2 * ATILE2;
    char* Blp = Bhp + W2T;
    for (int i = tid; i < 64 * H; i += 512) {
        const int k = i >> 6, n = i & 63;
        const float w = W2[k * 64 + n];
        const __nv_bfloat16 h = __float2bfloat16(w);
        *(__nv_bfloat16*)(Bhp + n * SA + k * 2) = h;
        *(__nv_bfloat16*)(Blp + n * SA + k * 2) = __float2bfloat16(w - __bfloat162float(h));
    }
    if (tid < 64) { s_w3[tid] = W3[tid]; s_b2[tid] = b2[tid]; }
    const float b3v = __ldg(b3);
    __syncthreads();

    const uint32_t AhA = smem_u32(Ahp), AlA = smem_u32(Alp);
    const uint32_t BhA = smem_u32(Bhp), BlA = smem_u32(Blp);
    const int rbw = (warp & 7) * 32;
    const int ch  = warp >> 3;

    for (int tile = blockIdx.x; tile < NUM_TX / 256; tile += gridDim.x) {
        const int rb = tile * 256;
        if (tid < 256) s_out[tid] = 0.0f;
        {
            const int r = tid >> 1, hf = tid & 1;
            const float4* src = (const float4*)(g_h1 + (size_t)(rb + r) * H) + hf * 16;
            char* ah = Ahp + r * SA + hf * 128;
            char* al = Alp + r * SA + hf * 128;
            #pragma unroll
            for (int j = 0; j < 16; j++) {
                float4 v = __ldg(src + j);
                v.x = fmaxf(v.x, 0.0f); v.y = fmaxf(v.y, 0.0f);
                v.z = fmaxf(v.z, 0.0f); v.w = fmaxf(v.w, 0.0f);
                uint32_t hi[2], lo[2];
                split4(v, hi, lo);
                *(uint32_t*)(ah + j * 8)     = hi[0];
                *(uint32_t*)(ah + j * 8 + 4) = hi[1];
                *(uint32_t*)(al + j * 8)     = lo[0];
                *(uint32_t*)(al + j * 8 + 4) = lo[1];
            }
        }
        __syncthreads();

        float acc[2][4][4];
        #pragma unroll
        for (int mt = 0; mt < 2; mt++)
            #pragma unroll
            for (int nt = 0; nt < 4; nt++)
                #pragma unroll
                for (int q = 0; q < 4; q++) acc[mt][nt][q] = 0.0f;

        {
            const uint32_t arow = rbw + (lane & 15);
            const uint32_t aqof = (lane >> 4) * 16;
            const uint32_t brow = ch * 32 + ((lane >> 4) * 8) + (lane & 7);
            const uint32_t bqof = ((lane >> 3) & 1) * 16;
            #pragma unroll
            for (int ks = 0; ks < 8; ks++) {
                const uint32_t kb = ks * 32;
                uint32_t ah[2][4], al[2][4], bh_[2][4], bl_[2][4];
                #pragma unroll
                for (int mt = 0; mt < 2; mt++) {
                    const uint32_t ao = (arow + mt * 16) * SA + kb + aqof;
                    ldmx4(ah[mt], AhA + ao);
                    ldmx4(al[mt], AlA + ao);
                }
                #pragma unroll
                for (int np = 0; np < 2; np++) {
                    const uint32_t bo = (brow + np * 16) * SA + kb + bqof;
                    ldmx4(bh_[np], BhA + bo);
                    ldmx4(bl_[np], BlA + bo);
                }
                #pragma unroll
                for (int np = 0; np < 2; np++)
                    #pragma unroll
                    for (int sb = 0; sb < 2; sb++) {
                        const int nt = np * 2 + sb;
                        #pragma unroll
                        for (int mt = 0; mt < 2; mt++) {
                            mma_bf16(acc[mt][nt], ah[mt], bh_[np][sb*2], bh_[np][sb*2+1]);
                            mma_bf16(acc[mt][nt], al[mt], bh_[np][sb*2], bh_[np][sb*2+1]);
                            mma_bf16(acc[mt][nt], ah[mt], bl_[np][sb*2], bl_[np][sb*2+1]);
                        }
                    }
            }
        }

        #pragma unroll
        for (int mt = 0; mt < 2; mt++) {
            const int row0 = rbw + mt * 16 + (lane >> 2), row1 = row0 + 8;
            float p0 = 0.0f, p1 = 0.0f;
            #pragma unroll
            for (int nt = 0; nt < 4; nt++) {
                const int col = ch * 32 + nt * 8 + (lane & 3) * 2;
                p0 += fmaxf(acc[mt][nt][0] + s_b2[col],     0.0f) * s_w3[col]
                    + fmaxf(acc[mt][nt][1] + s_b2[col + 1], 0.0f) * s_w3[col + 1];
                p1 += fmaxf(acc[mt][nt][2] + s_b2[col],     0.0f) * s_w3[col]
                    + fmaxf(acc[mt][nt][3] + s_b2[col + 1], 0.0f) * s_w3[col + 1];
            }
            #pragma unroll
            for (int o = 1; o < 4; o <<= 1) {
                p0 += __shfl_xor_sync(0xffffffffu, p0, o);
                p1 += __shfl_xor_sync(0xffffffffu, p1, o);
            }
            if ((lane & 3) == 0) {
                atomicAdd(&s_out[row0], p0);
                atomicAdd(&s_out[row1], p1);
            }
        }
        __syncthreads();
        if (tid < 256) out[rb + tid] = s_out[tid] + b3v;
        __syncthreads();
    }
}

// ================= host launcher =============================================
extern "C" void kernel_launch(void* const* d_in, const int* in_sizes, int n_in,
                              void* d_out, int out_size) {
    const float* tx_x = (const float*)d_in[0];
    const float* emb  = (const float*)d_in[1];
    const int*   eidx = (const int*)  d_in[2];
    const int*   esrc = (const int*)  d_in[3];
    const int*   edst = (const int*)  d_in[4];
    const float* Wq = (const float*)d_in[5],  *bq = (const float*)d_in[6];
    const float* Wk = (const float*)d_in[7];
    const float* Wv = (const float*)d_in[9],  *bv = (const float*)d_in[10];
    const float* Ws = (const float*)d_in[11], *bs = (const float*)d_in[12];
    const float* lns = (const float*)d_in[13], *lnb = (const float*)d_in[14];
    const float* W1 = (const float*)d_in[15], *b1 = (const float*)d_in[16];
    const float* W2 = (const float*)d_in[17], *b2 = (const float*)d_in[18];
    const float* W3 = (const float*)d_in[19], *b3 = (const float*)d_in[20];
    float* out = (float*)d_out;

    const int SM256    = 2 * ATILE2 + 2 * BTILE + 1024;  // 209920
    const int MLP_SMEM = 2 * ATILE2 + 2 * W2T + 1024;    // 175104
    cudaFuncSetAttribute(k_init_mma, cudaFuncAttributeMaxDynamicSharedMemorySize, SM256);
    cudaFuncSetAttribute(k_z_mma,    cudaFuncAttributeMaxDynamicSharedMemorySize, SM256);
    cudaFuncSetAttribute(k_fused,    cudaFuncAttributeMaxDynamicSharedMemorySize, SM256);
    cudaFuncSetAttribute(k_mlp_mma,  cudaFuncAttributeMaxDynamicSharedMemorySize, MLP_SMEM);

    k_prep <<<128, 128>>>(Wq, Wk, bq);
    k_mkimg<<<2 + T_TYPES, 256>>>(Wv, Ws, W1);

    k_zero_deg<<<(T_TYPES * N_ENT + 255) / 256, 256>>>();
    k_count   <<<(T_TYPES * NE + 255) / 256, 256>>>(edst);
    k_scanA   <<<T_TYPES * 64, 256>>>();
    k_scanB   <<<T_TYPES, 64>>>();
    k_scanC   <<<T_TYPES * 64, 256>>>();
    k_fill    <<<(T_TYPES * NE + 255) / 256, 256>>>(esrc, edst);

    k_init_mma<<<148, 512, SM256>>>(tx_x, W1, b1);

    k_z_mma  <<<148, 512, SM256>>>(emb, eidx);
    k_attn   <<<T_TYPES * (N_ENT / 8), 256>>>();
    k_fused  <<<148, 512, SM256>>>(bv, bs, lns, lnb);
    k_h1add_all<<<NUM_TX / 8, 256>>>();

    k_mlp_mma<<<148, 512, MLP_SMEM>>>(W2, b2, W3, b3, out);
}

// round 15
// speedup vs baseline: 1.0975x; 1.0057x over previous
#include <cuda_runtime.h>
#include <cuda_bf16.h>
#include <math.h>
#include <stdint.h>

#define T_TYPES 11
#define NUM_TX  131072
#define N_ENT   131072
#define NE      262144
#define H       128
#define TXF     394
#define LN_EPS  1e-5f
#define INV_SQRT_D 0.08838834764831845f   // 1/sqrt(128)

// bf16 tile strides (bytes): 128 bf16 = 256B + 16B pad -> conflict-free ldmatrix
#define SA 272
#define ATILE2  69632     // 256 rows * 272B
#define BTILE   34816     // 128 n-rows * 272B
#define W2T     17408     // 64 n-rows * 272B

// ---------------- scratch (device globals; no cudaMalloc allowed) ----------
__device__ uint32_t g_zb [T_TYPES][(size_t)N_ENT * 64];  // bf16x2 z rows
__device__ float g_x   [T_TYPES][(size_t)N_ENT * H];
__device__ float g_xagg[T_TYPES][(size_t)N_ENT * H];
__device__ float g_hw  [T_TYPES][(size_t)N_ENT * H];
__device__ float g_c   [T_TYPES][N_ENT];
__device__ float g_h1  [(size_t)NUM_TX * H];
__device__ float g_weff[H * H];               // Wz[k][n]
__device__ float g_wkbq[H];

// precomputed split-bf16 swizzled B images: [hi BTILE][lo BTILE]
__device__ uint4 g_img_v [(2 * BTILE) / 16];
__device__ uint4 g_img_s [(2 * BTILE) / 16];
__device__ uint4 g_img_w1[T_TYPES][(2 * BTILE) / 16];

// CSR over dst, per type
__device__ int g_deg [T_TYPES][N_ENT];
__device__ int g_ptr [T_TYPES][N_ENT];
__device__ int g_cur [T_TYPES][N_ENT];
__device__ int g_col [T_TYPES][NE];
__device__ int g_bsum[T_TYPES][64];

// ================= helpers ===================================================
__device__ __forceinline__ uint32_t smem_u32(const void* p) {
    uint32_t a;
    asm("{ .reg .u64 t; cvta.to.shared.u64 t, %1; cvt.u32.u64 %0, t; }" : "=r"(a) : "l"(p));
    return a;
}
__device__ __forceinline__ void ldmx4(uint32_t* r, uint32_t addr) {
    asm volatile("ldmatrix.sync.aligned.m8n8.x4.shared.b16 {%0,%1,%2,%3}, [%4];"
        : "=r"(r[0]), "=r"(r[1]), "=r"(r[2]), "=r"(r[3]) : "r"(addr));
}
__device__ __forceinline__ void mma_bf16(float* c, const uint32_t* a, uint32_t b0, uint32_t b1) {
    asm volatile("mma.sync.aligned.m16n8k16.row.col.f32.bf16.bf16.f32 "
        "{%0,%1,%2,%3}, {%4,%5,%6,%7}, {%8,%9}, {%0,%1,%2,%3};"
        : "+f"(c[0]), "+f"(c[1]), "+f"(c[2]), "+f"(c[3])
        : "r"(a[0]), "r"(a[1]), "r"(a[2]), "r"(a[3]), "r"(b0), "r"(b1));
}
__device__ __forceinline__ uint32_t bfpack(float a, float b) {
    __nv_bfloat162 t = __floats2bfloat162_rn(a, b);
    return reinterpret_cast<uint32_t&>(t);
}
__device__ __forceinline__ void split4(float4 v, uint32_t* hi, uint32_t* lo) {
    __nv_bfloat16 hx = __float2bfloat16(v.x), hy = __float2bfloat16(v.y);
    __nv_bfloat16 hz = __float2bfloat16(v.z), hw = __float2bfloat16(v.w);
    __nv_bfloat162 h01; h01.x = hx; h01.y = hy;
    __nv_bfloat162 h23; h23.x = hz; h23.y = hw;
    hi[0] = reinterpret_cast<uint32_t&>(h01);
    hi[1] = reinterpret_cast<uint32_t&>(h23);
    lo[0] = bfpack(v.x - __bfloat162float(hx), v.y - __bfloat162float(hy));
    lo[1] = bfpack(v.z - __bfloat162float(hz), v.w - __bfloat162float(hw));
}
__device__ __forceinline__ void split2(float a, float b, uint32_t& hi, uint32_t& lo) {
    __nv_bfloat16 ha = __float2bfloat16(a), hb = __float2bfloat16(b);
    __nv_bfloat162 hp; hp.x = ha; hp.y = hb;
    hi = reinterpret_cast<uint32_t&>(hp);
    lo = bfpack(a - __bfloat162float(ha), b - __bfloat162float(hb));
}
__device__ __forceinline__ void conv_B(const float* __restrict__ W, char* bh, char* bl,
                                       int tid, int nthr) {
    for (int i = tid; i < H * H; i += nthr) {
        const int k = i >> 7, n = i & 127;
        const float w = W[i];
        const __nv_bfloat16 h = __float2bfloat16(w);
        *(__nv_bfloat16*)(bh + n * SA + k * 2) = h;
        *(__nv_bfloat16*)(bl + n * SA + k * 2) = __float2bfloat16(w - __bfloat162float(h));
    }
}
__device__ __forceinline__ void copy_img(const uint4* __restrict__ img, char* bh, int tid) {
    uint4* d = (uint4*)bh;
    for (int i = tid; i < (2 * BTILE) / 16; i += 512) d[i] = __ldg(img + i);
}

// ================= prep: Wz = Wk Wq^T, wkbq = Wk bq ==========================
__global__ void k_prep(const float* __restrict__ Wq, const float* __restrict__ Wk,
                       const float* __restrict__ bq) {
    __shared__ float wkrow[H];
    const int b = blockIdx.x, a = threadIdx.x;
    wkrow[a] = Wk[b * H + a];
    __syncthreads();
    float s = 0.0f;
    #pragma unroll 4
    for (int j = 0; j < H; j++) s = fmaf(wkrow[j], Wq[a * H + j], s);
    g_weff[b * H + a] = s;
    if (b == 0) {
        float t = 0.0f;
        for (int j = 0; j < H; j++) t = fmaf(Wk[a * H + j], bq[j], t);
        g_wkbq[a] = t;
    }
}

// ================= build split-bf16 B images =================================
__global__ void k_mkimg(const float* __restrict__ Wv, const float* __restrict__ Ws,
                        const float* __restrict__ W1) {
    const int b = blockIdx.x;
    const float* W;
    uint8_t* img;
    if (b == 0)      { W = Wv; img = (uint8_t*)g_img_v; }
    else if (b == 1) { W = Ws; img = (uint8_t*)g_img_s; }
    else             { W = W1 + (size_t)(TXF + (b - 2) * H) * H;
                       img = (uint8_t*)g_img_w1[b - 2]; }
    for (int i = threadIdx.x; i < H * H; i += 256) {
        const int k = i >> 7, n = i & 127;
        const float w = W[i];
        const __nv_bfloat16 h = __float2bfloat16(w);
        *(__nv_bfloat16*)(img + n * SA + k * 2) = h;
        *(__nv_bfloat16*)(img + BTILE + n * SA + k * 2) =
            __float2bfloat16(w - __bfloat162float(h));
    }
}

// ================= CSR build =================================================
__global__ void k_zero_deg() {
    const int i = blockIdx.x * blockDim.x + threadIdx.x;
    if (i < T_TYPES * N_ENT) ((int*)g_deg)[i] = 0;
}
__global__ void k_count(const int* __restrict__ edst) {
    const int i = blockIdx.x * blockDim.x + threadIdx.x;
    if (i >= T_TYPES * NE) return;
    const int t = i / NE;
    atomicAdd(&g_deg[t][edst[i]], 1);
}
__global__ void k_scanA() {
    const int t = blockIdx.x >> 6, c = blockIdx.x & 63;
    const int base = c * 2048, tid = threadIdx.x;
    int v[8], s = 0;
    #pragma unroll
    for (int j = 0; j < 8; j++) { v[j] = g_deg[t][base + tid * 8 + j]; s += v[j]; }
    __shared__ int sm[256];
    sm[tid] = s; __syncthreads();
    for (int off = 1; off < 256; off <<= 1) {
        int x = (tid >= off) ? sm[tid - off] : 0;
        __syncthreads();
        sm[tid] += x;
        __syncthreads();
    }
    int run = (tid == 0) ? 0 : sm[tid - 1];
    if (tid == 255) g_bsum[t][c] = sm[255];
    #pragma unroll
    for (int j = 0; j < 8; j++) { g_ptr[t][base + tid * 8 + j] = run; run += v[j]; }
}
__global__ void k_scanB() {
    const int t = blockIdx.x, tid = threadIdx.x;
    __shared__ int sm[64];
    sm[tid] = g_bsum[t][tid]; __syncthreads();
    for (int off = 1; off < 64; off <<= 1) {
        int x = (tid >= off) ? sm[tid - off] : 0;
        __syncthreads();
        sm[tid] += x;
        __syncthreads();
    }
    g_bsum[t][tid] = (tid == 0) ? 0 : sm[tid - 1];
}
__global__ void k_scanC() {
    const int t = blockIdx.x >> 6, c = blockIdx.x & 63;
    const int base = c * 2048, tid = threadIdx.x;
    const int add = g_bsum[t][c];
    #pragma unroll
    for (int j = 0; j < 8; j++) {
        const int i = base + tid * 8 + j;
        const int p = g_ptr[t][i] + add;
        g_ptr[t][i] = p;
        g_cur[t][i] = p;
    }
}
__global__ void k_fill(const int* __restrict__ esrc, const int* __restrict__ edst) {
    const int i = blockIdx.x * blockDim.x + threadIdx.x;
    if (i >= T_TYPES * NE) return;
    const int t = i / NE;
    const int slot = atomicAdd(&g_cur[t][edst[i]], 1);
    g_col[t][slot] = esrc[i];
}

// ================= MMA core (256-row tile, acc[2][8][4], 16 warps) ==========
#define MMA_TILE256(AhA, AlA, BhA, BlA, acc, rbw, ch, lane)                          \
    {                                                                                 \
        const uint32_t arow = (rbw) + ((lane) & 15);                                  \
        const uint32_t aqof = ((lane) >> 4) * 16;                                     \
        const uint32_t brow = (ch) * 64 + (((lane) >> 4) * 8) + ((lane) & 7);         \
        const uint32_t bqof = (((lane) >> 3) & 1) * 16;                               \
        _Pragma("unroll")                                                             \
        for (int ks = 0; ks < 8; ks++) {                                              \
            const uint32_t kb = ks * 32;                                              \
            uint32_t ah[2][4], al[2][4], bf[4][4];                                    \
            _Pragma("unroll")                                                         \
            for (int mt = 0; mt < 2; mt++) {                                          \
                const uint32_t ao = (arow + mt * 16) * SA + kb + aqof;                \
                ldmx4(ah[mt], (AhA) + ao);                                            \
                ldmx4(al[mt], (AlA) + ao);                                            \
            }                                                                         \
            _Pragma("unroll")                                                         \
            for (int np = 0; np < 4; np++)                                            \
                ldmx4(bf[np], (BhA) + (brow + np * 16) * SA + kb + bqof);             \
            _Pragma("unroll")                                                         \
            for (int np = 0; np < 4; np++)                                            \
                _Pragma("unroll")                                                     \
                for (int sb = 0; sb < 2; sb++) {                                      \
                    const int nt = np * 2 + sb;                                       \
                    _Pragma("unroll")                                                 \
                    for (int mt = 0; mt < 2; mt++) {                                  \
                        mma_bf16(acc[mt][nt], ah[mt], bf[np][sb*2], bf[np][sb*2+1]);  \
                        mma_bf16(acc[mt][nt], al[mt], bf[np][sb*2], bf[np][sb*2+1]);  \
                    }                                                                 \
                }                                                                     \
            _Pragma("unroll")                                                         \
            for (int np = 0; np < 4; np++)                                            \
                ldmx4(bf[np], (BlA) + (brow + np * 16) * SA + kb + bqof);             \
            _Pragma("unroll")                                                         \
            for (int np = 0; np < 4; np++)                                            \
                _Pragma("unroll")                                                     \
                for (int sb = 0; sb < 2; sb++) {                                      \
                    const int nt = np * 2 + sb;                                       \
                    _Pragma("unroll")                                                 \
                    for (int mt = 0; mt < 2; mt++)                                    \
                        mma_bf16(acc[mt][nt], ah[mt], bf[np][sb*2], bf[np][sb*2+1]);  \
                }                                                                     \
        }                                                                             \
    }

// ================= init_h1 via MMA: b1 + tx_x @ W1[0:394] ====================
__global__ void __launch_bounds__(512, 1) k_init_mma(const float* __restrict__ tx,
                                                     const float* __restrict__ W1,
                                                     const float* __restrict__ b1) {
    extern __shared__ char dsraw[];
    __shared__ float s_b1[H];
    const uint32_t raw  = smem_u32(dsraw);
    const uint32_t base = (raw + 1023u) & ~1023u;
    char* dsm = dsraw + (base - raw);
    const int tid = threadIdx.x, warp = tid >> 5, lane = tid & 31;

    char* Ahp = dsm;
    char* Alp = dsm + ATILE2;
    char* Bhp = dsm + 2 * ATILE2;
    char* Blp = Bhp + BTILE;
    const uint32_t AhA = smem_u32(Ahp), AlA = smem_u32(Alp);
    const uint32_t BhA = smem_u32(Bhp), BlA = smem_u32(Blp);

    if (tid < H) s_b1[tid] = b1[tid];

    const int rbw = (warp & 7) * 32;
    const int ch  = warp >> 3;

    for (int tile = blockIdx.x; tile < NUM_TX / 256; tile += gridDim.x) {
        const int rb = tile * 256;
        float acc[2][8][4];
        #pragma unroll
        for (int mt = 0; mt < 2; mt++)
            #pragma unroll
            for (int nt = 0; nt < 8; nt++)
                #pragma unroll
                for (int q = 0; q < 4; q++) acc[mt][nt][q] = 0.0f;

        for (int chunk = 0; chunk < 4; chunk++) {
            __syncthreads();
            const int kcols = (chunk < 3) ? 128 : 16;
            for (int i = tid; i < kcols * H; i += 512) {
                const int k = i >> 7, n = i & 127;
                const int kk = chunk * 128 + k;
                const float w = (kk < TXF) ? W1[(size_t)kk * H + n] : 0.0f;
                const __nv_bfloat16 h = __float2bfloat16(w);
                *(__nv_bfloat16*)(Bhp + n * SA + k * 2) = h;
                *(__nv_bfloat16*)(Blp + n * SA + k * 2) =
                    __float2bfloat16(w - __bfloat162float(h));
            }
            const int r = tid >> 1, hf = tid & 1;
            const float* rowp = tx + (size_t)(rb + r) * TXF;
            if (chunk < 3) {
                const float2* src = (const float2*)(rowp + chunk * 128 + hf * 64);
                char* ah = Ahp + r * SA + hf * 128;
                char* al = Alp + r * SA + hf * 128;
                #pragma unroll
                for (int j = 0; j < 16; j++) {
                    const float2 a = __ldg(src + j * 2);
                    const float2 b = __ldg(src + j * 2 + 1);
                    float4 v = { a.x, a.y, b.x, b.y };
                    uint32_t hi[2], lo[2];
                    split4(v, hi, lo);
                    *(uint32_t*)(ah + j * 8)     = hi[0];
                    *(uint32_t*)(ah + j * 8 + 4) = hi[1];
                    *(uint32_t*)(al + j * 8)     = lo[0];
                    *(uint32_t*)(al + j * 8 + 4) = lo[1];
                }
            } else {
                float vals[8];
                #pragma unroll
                for (int j = 0; j < 8; j++) {
                    const int c = 384 + hf * 8 + j;
                    vals[j] = (c < TXF) ? __ldg(rowp + c) : 0.0f;
                }
                char* ah = Ahp + r * SA + hf * 16;
                char* al = Alp + r * SA + hf * 16;
                #pragma unroll
                for (int p = 0; p < 4; p++) {
                    float4 v = { vals[p*2], vals[p*2+1], 0.0f, 0.0f };
                    uint32_t hi[2], lo[2];
                    split4(v, hi, lo);
                    *(uint32_t*)(ah + p * 4) = hi[0];
                    *(uint32_t*)(al + p * 4) = lo[0];
                }
            }
            __syncthreads();

            const uint32_t arow = rbw + (lane & 15);
            const uint32_t aqof = (lane >> 4) * 16;
            const uint32_t brow = ch * 64 + ((lane >> 4) * 8) + (lane & 7);
            const uint32_t bqof = ((lane >> 3) & 1) * 16;
            const int nks = (chunk < 3) ? 8 : 1;
            for (int ks = 0; ks < nks; ks++) {
                const uint32_t kb = ks * 32;
                uint32_t ah[2][4], al[2][4], bf[4][4];
                #pragma unroll
                for (int mt = 0; mt < 2; mt++) {
                    const uint32_t ao = (arow + mt * 16) * SA + kb + aqof;
                    ldmx4(ah[mt], AhA + ao);
                    ldmx4(al[mt], AlA + ao);
                }
                #pragma unroll
                for (int np = 0; np < 4; np++)
                    ldmx4(bf[np], BhA + (brow + np * 16) * SA + kb + bqof);
                #pragma unroll
                for (int np = 0; np < 4; np++)
                    #pragma unroll
                    for (int sb = 0; sb < 2; sb++) {
                        const int nt = np * 2 + sb;
                        #pragma unroll
                        for (int mt = 0; mt < 2; mt++) {
                            mma_bf16(acc[mt][nt], ah[mt], bf[np][sb*2], bf[np][sb*2+1]);
                            mma_bf16(acc[mt][nt], al[mt], bf[np][sb*2], bf[np][sb*2+1]);
                        }
                    }
                #pragma unroll
                for (int np = 0; np < 4; np++)
                    ldmx4(bf[np], BlA + (brow + np * 16) * SA + kb + bqof);
                #pragma unroll
                for (int np = 0; np < 4; np++)
                    #pragma unroll
                    for (int sb = 0; sb < 2; sb++) {
                        const int nt = np * 2 + sb;
                        #pragma unroll
                        for (int mt = 0; mt < 2; mt++)
                            mma_bf16(acc[mt][nt], ah[mt], bf[np][sb*2], bf[np][sb*2+1]);
                    }
            }
        }
        #pragma unroll
        for (int mt = 0; mt < 2; mt++) {
            const int row0 = rb + rbw + mt * 16 + (lane >> 2);
            #pragma unroll
            for (int nt = 0; nt < 8; nt++) {
                const int col = ch * 64 + nt * 8 + (lane & 3) * 2;
                const float b0 = s_b1[col], b1v = s_b1[col + 1];
                float2 v0 = { acc[mt][nt][0] + b0, acc[mt][nt][1] + b1v };
                float2 v1 = { acc[mt][nt][2] + b0, acc[mt][nt][3] + b1v };
                *(float2*)(g_h1 + (size_t)row0 * H + col)       = v0;
                *(float2*)(g_h1 + (size_t)(row0 + 8) * H + col) = v1;
            }
        }
    }
}

// ====== Z GEMM (ALL types): gather x, zb = bf16(x@Wz), c = x.wkbq ============
__global__ void __launch_bounds__(512, 1) k_z_mma(const float* __restrict__ emb,
                                                  const int* __restrict__ idx) {
    extern __shared__ char dsraw[];
    __shared__ float s_wkbq[H];
    const uint32_t raw  = smem_u32(dsraw);
    const uint32_t base = (raw + 1023u) & ~1023u;
    char* dsm = dsraw + (base - raw);
    const int tid = threadIdx.x, warp = tid >> 5, lane = tid & 31;

    char* Ahp = dsm;
    char* Alp = dsm + ATILE2;
    char* Bhp = dsm + 2 * ATILE2;
    char* Blp = Bhp + BTILE;
    conv_B(g_weff, Bhp, Blp, tid, 512);
    if (tid < H) s_wkbq[tid] = g_wkbq[tid];
    __syncthreads();

    const uint32_t AhA = smem_u32(Ahp), AlA = smem_u32(Alp);
    const uint32_t BhA = smem_u32(Bhp), BlA = smem_u32(Blp);
    const int rbw = (warp & 7) * 32;
    const int ch  = warp >> 3;

    for (int tile = blockIdx.x; tile < T_TYPES * (N_ENT / 256); tile += gridDim.x) {
        const int t  = tile >> 9;                 // 512 tiles per type
        const int rb = (tile & 511) * 256;
        const float* embt = emb + (size_t)t * N_ENT * H;
        const int*   idxt = idx + (size_t)t * N_ENT;
        {
            const int r = tid >> 1, hf = tid & 1;
            const int e = __ldg(idxt + rb + r);
            const float4* src = (const float4*)(embt + (size_t)e * H) + hf * 16;
            float4* xdst = (float4*)(g_x[t] + (size_t)(rb + r) * H) + hf * 16;
            char* ah = Ahp + r * SA + hf * 128;
            char* al = Alp + r * SA + hf * 128;
            float cp = 0.0f;
            #pragma unroll
            for (int j = 0; j < 16; j++) {
                const float4 v = __ldg(src + j);
                uint32_t hi[2], lo[2];
                split4(v, hi, lo);
                *(uint32_t*)(ah + j * 8)     = hi[0];
                *(uint32_t*)(ah + j * 8 + 4) = hi[1];
                *(uint32_t*)(al + j * 8)     = lo[0];
                *(uint32_t*)(al + j * 8 + 4) = lo[1];
                xdst[j] = v;
                const float* wb = s_wkbq + hf * 64 + j * 4;
                cp += v.x * wb[0] + v.y * wb[1] + v.z * wb[2] + v.w * wb[3];
            }
            cp += __shfl_xor_sync(0xffffffffu, cp, 1);
            if (hf == 0) g_c[t][rb + r] = cp;
        }
        __syncthreads();

        float acc[2][8][4];
        #pragma unroll
        for (int mt = 0; mt < 2; mt++)
            #pragma unroll
            for (int nt = 0; nt < 8; nt++)
                #pragma unroll
                for (int q = 0; q < 4; q++) acc[mt][nt][q] = 0.0f;

        MMA_TILE256(AhA, AlA, BhA, BlA, acc, rbw, ch, lane);

        #pragma unroll
        for (int mt = 0; mt < 2; mt++) {
            const int row0 = rb + rbw + mt * 16 + (lane >> 2);
            #pragma unroll
            for (int nt = 0; nt < 8; nt++) {
                const int col = ch * 64 + nt * 8 + (lane & 3) * 2;
                g_zb[t][(size_t)row0 * 64 + (col >> 1)] =
                    bfpack(acc[mt][nt][0], acc[mt][nt][1]);
                g_zb[t][(size_t)(row0 + 8) * 64 + (col >> 1)] =
                    bfpack(acc[mt][nt][2], acc[mt][nt][3]);
            }
        }
        __syncthreads();
    }
}

// ================= attention aggregation (ALL types; warp per dst) ===========
__global__ void __launch_bounds__(256) k_attn() {
    const int warp = threadIdx.x >> 5, lane = threadIdx.x & 31;
    const int t = blockIdx.x >> 14;               // 16384 blocks per type
    const int d = (blockIdx.x & 16383) * 8 + warp;
    const float4 xd4 = ((const float4*)(g_x[t] + (size_t)d * H))[lane];
    const int start = g_ptr[t][d], deg = g_deg[t][d];

    float den = 0.0f;
    float4 acc = {0.0f, 0.0f, 0.0f, 0.0f};
    int s_next = (deg > 0) ? __ldg(&g_col[t][start]) : 0;
    float c_next = (deg > 0) ? __ldg(&g_c[t][s_next]) : 0.0f;
    for (int e = 0; e < deg; e++) {
        const int s = s_next;
        const float cs = c_next;
        if (e + 1 < deg) {
            s_next = __ldg(&g_col[t][start + e + 1]);
            c_next = __ldg(&g_c[t][s_next]);
        }
        const uint2 z2 = *((const uint2*)(g_zb[t] + (size_t)s * 64) + lane);
        const float2 z0 = __bfloat1622float2(*(const __nv_bfloat162*)&z2.x);
        const float2 z1 = __bfloat1622float2(*(const __nv_bfloat162*)&z2.y);
        const float4 x4 = ((const float4*)(g_x[t] + (size_t)s * H))[lane];
        float dot = xd4.x * z0.x + xd4.y * z0.y + xd4.z * z1.x + xd4.w * z1.y;
        #pragma unroll
        for (int o = 16; o; o >>= 1) dot += __shfl_xor_sync(0xffffffffu, dot, o);
        const float w = expf((dot + cs) * INV_SQRT_D);
        den += w;
        acc.x += w * x4.x; acc.y += w * x4.y; acc.z += w * x4.z; acc.w += w * x4.w;
    }
    const float inv = (deg > 0) ? 1.0f / den : 0.0f;
    float4 o4 = { acc.x * inv, acc.y * inv, acc.z * inv, acc.w * inv };
    ((float4*)(g_xagg[t] + (size_t)d * H))[lane] = o4;
}

// ===== fused (ALL types): h = LN(xagg@Wv + x@Ws + bv+bs)*g+b; hw = h@W1_t ====
__global__ void __launch_bounds__(512, 1) k_fused(
    const float* __restrict__ bv, const float* __restrict__ bs,
    const float* __restrict__ lns, const float* __restrict__ lnb) {
    extern __shared__ char dsraw[];
    __shared__ float s_bias[H], s_g[H], s_b[H];
    __shared__ float sS1[256], sS2[256], sMu[256], sRstd[256];
    const uint32_t raw  = smem_u32(dsraw);
    const uint32_t base = (raw + 1023u) & ~1023u;
    char* dsm = dsraw + (base - raw);
    const int tid = threadIdx.x, warp = tid >> 5, lane = tid & 31;

    char* Ahp = dsm;
    char* Alp = dsm + ATILE2;
    char* Bhp = dsm + 2 * ATILE2;
    const uint32_t AhA = smem_u32(Ahp), AlA = smem_u32(Alp);
    const uint32_t BhA = smem_u32(Bhp), BlA = BhA + BTILE;
    const int rbw = (warp & 7) * 32;
    const int ch  = warp >> 3;

    for (int tile = blockIdx.x; tile < T_TYPES * (N_ENT / 256); tile += gridDim.x) {
        const int t  = tile >> 9;
        const int rb = (tile & 511) * 256;
        float acc[2][8][4];
        #pragma unroll
        for (int mt = 0; mt < 2; mt++)
            #pragma unroll
            for (int nt = 0; nt < 8; nt++)
                #pragma unroll
                for (int q = 0; q < 4; q++) acc[mt][nt][q] = 0.0f;

        // ---- stage 1: B <- Wv image, gather xagg, zero stats, LN params
        copy_img(g_img_v, Bhp, tid);
        {
            const int r = tid >> 1, hf = tid & 1;
            const float4* src = (const float4*)(g_xagg[t] + (size_t)(rb + r) * H) + hf * 16;
            char* ah = Ahp + r * SA + hf * 128;
            char* al = Alp + r * SA + hf * 128;
            #pragma unroll
            for (int j = 0; j < 16; j++) {
                uint32_t hi[2], lo[2];
                split4(__ldg(src + j), hi, lo);
                *(uint32_t*)(ah + j * 8)     = hi[0];
                *(uint32_t*)(ah + j * 8 + 4) = hi[1];
                *(uint32_t*)(al + j * 8)     = lo[0];
                *(uint32_t*)(al + j * 8 + 4) = lo[1];
            }
        }
        if (tid < 256) { sS1[tid] = 0.0f; sS2[tid] = 0.0f; }
        if (tid < H) {
            s_bias[tid] = __ldg(bv + tid) + __ldg(bs + tid);
            s_g[tid] = __ldg(lns + t * H + tid);
            s_b[tid] = __ldg(lnb + t * H + tid);
        }
        __syncthreads();
        MMA_TILE256(AhA, AlA, BhA, BlA, acc, rbw, ch, lane);
        __syncthreads();

        // ---- stage 2: B <- Ws image, gather x
        copy_img(g_img_s, Bhp, tid);
        {
            const int r = tid >> 1, hf = tid & 1;
            const float4* src = (const float4*)(g_x[t] + (size_t)(rb + r) * H) + hf * 16;
            char* ah = Ahp + r * SA + hf * 128;
            char* al = Alp + r * SA + hf * 128;
            #pragma unroll
            for (int j = 0; j < 16; j++) {
                uint32_t hi[2], lo[2];
                split4(__ldg(src + j), hi, lo);
                *(uint32_t*)(ah + j * 8)     = hi[0];
                *(uint32_t*)(ah + j * 8 + 4) = hi[1];
                *(uint32_t*)(al + j * 8)     = lo[0];
                *(uint32_t*)(al + j * 8 + 4) = lo[1];
            }
        }
        __syncthreads();
        MMA_TILE256(AhA, AlA, BhA, BlA, acc, rbw, ch, lane);

        // ---- bias + LN stats over 256 local rows
        const int lr = lane >> 2;
        #pragma unroll
        for (int mt = 0; mt < 2; mt++) {
            const int row0 = rbw + mt * 16 + lr, row1 = row0 + 8;
            float s1a = 0, s2a = 0, s1b = 0, s2b = 0;
            #pragma unroll
            for (int nt = 0; nt < 8; nt++) {
                const int col = ch * 64 + nt * 8 + (lane & 3) * 2;
                acc[mt][nt][0] += s_bias[col]; acc[mt][nt][1] += s_bias[col + 1];
                acc[mt][nt][2] += s_bias[col]; acc[mt][nt][3] += s_bias[col + 1];
                s1a += acc[mt][nt][0] + acc[mt][nt][1];
                s2a += acc[mt][nt][0] * acc[mt][nt][0] + acc[mt][nt][1] * acc[mt][nt][1];
                s1b += acc[mt][nt][2] + acc[mt][nt][3];
                s2b += acc[mt][nt][2] * acc[mt][nt][2] + acc[mt][nt][3] * acc[mt][nt][3];
            }
            #pragma unroll
            for (int o = 1; o < 4; o <<= 1) {
                s1a += __shfl_xor_sync(0xffffffffu, s1a, o);
                s2a += __shfl_xor_sync(0xffffffffu, s2a, o);
                s1b += __shfl_xor_sync(0xffffffffu, s1b, o);
                s2b += __shfl_xor_sync(0xffffffffu, s2b, o);
            }
            if ((lane & 3) == 0) {
                atomicAdd(&sS1[row0], s1a); atomicAdd(&sS2[row0], s2a);
                atomicAdd(&sS1[row1], s1b); atomicAdd(&sS2[row1], s2b);
            }
        }
        __syncthreads();
        if (tid < 256) {
            const float mu = sS1[tid] * (1.0f / H);
            const float var = sS2[tid] * (1.0f / H) - mu * mu;
            sMu[tid] = mu;
            sRstd[tid] = rsqrtf(var + LN_EPS);
        }
        __syncthreads();

        // ---- stage 3: h -> A tile (split bf16), B <- W1t image
        #pragma unroll
        for (int mt = 0; mt < 2; mt++) {
            const int row0 = rbw + mt * 16 + lr, row1 = row0 + 8;
            const float mu0 = sMu[row0], rs0 = sRstd[row0];
            const float mu1 = sMu[row1], rs1 = sRstd[row1];
            #pragma unroll
            for (int nt = 0; nt < 8; nt++) {
                const int col = ch * 64 + nt * 8 + (lane & 3) * 2;
                const float g0 = s_g[col], g1 = s_g[col + 1];
                const float b0 = s_b[col], b1v = s_b[col + 1];
                const float h00 = (acc[mt][nt][0] - mu0) * rs0 * g0 + b0;
                const float h01 = (acc[mt][nt][1] - mu0) * rs0 * g1 + b1v;
                const float h10 = (acc[mt][nt][2] - mu1) * rs1 * g0 + b0;
                const float h11 = (acc[mt][nt][3] - mu1) * rs1 * g1 + b1v;
                uint32_t hi, lo;
                split2(h00, h01, hi, lo);
                *(uint32_t*)(Ahp + row0 * SA + col * 2) = hi;
                *(uint32_t*)(Alp + row0 * SA + col * 2) = lo;
                split2(h10, h11, hi, lo);
                *(uint32_t*)(Ahp + row1 * SA + col * 2) = hi;
                *(uint32_t*)(Alp + row1 * SA + col * 2) = lo;
            }
        }
        copy_img(g_img_w1[t], Bhp, tid);
        __syncthreads();

        // ---- stage 3 GEMM: hw = h @ W1t
        #pragma unroll
        for (int mt = 0; mt < 2; mt++)
            #pragma unroll
            for (int nt = 0; nt < 8; nt++)
                #pragma unroll
                for (int q = 0; q < 4; q++) acc[mt][nt][q] = 0.0f;
        MMA_TILE256(AhA, AlA, BhA, BlA, acc, rbw, ch, lane);

        #pragma unroll
        for (int mt = 0; mt < 2; mt++) {
            const int row0 = rb + rbw + mt * 16 + lr;
            #pragma unroll
            for (int nt = 0; nt < 8; nt++) {
                const int col = ch * 64 + nt * 8 + (lane & 3) * 2;
                float2 v0 = { acc[mt][nt][0], acc[mt][nt][1] };
                float2 v1 = { acc[mt][nt][2], acc[mt][nt][3] };
                *(float2*)(g_hw[t] + (size_t)row0 * H + col)       = v0;
                *(float2*)(g_hw[t] + (size_t)(row0 + 8) * H + col) = v1;
            }
        }
        __syncthreads();
    }
}

// ====== h1[d] += sum over ALL types of sum_e hw_t[col[e]] (warp per row) =====
__global__ void __launch_bounds__(256) k_h1add_all() {
    const int warp = threadIdx.x >> 5, lane = threadIdx.x & 31;
    const int d = blockIdx.x * 8 + warp;
    float4 acc = {0.0f, 0.0f, 0.0f, 0.0f};
    #pragma unroll 1
    for (int t = 0; t < T_TYPES; t++) {
        const int start = g_ptr[t][d], deg = g_deg[t][d];
        const float* hwt = g_hw[t];
        int s_next = (deg > 0) ? __ldg(&g_col[t][start]) : 0;
        for (int e = 0; e < deg; e++) {
            const int s = s_next;
            if (e + 1 < deg) s_next = __ldg(&g_col[t][start + e + 1]);
            const float4 w4 = ((const float4*)(hwt + (size_t)s * H))[lane];
            acc.x += w4.x; acc.y += w4.y; acc.z += w4.z; acc.w += w4.w;
        }
    }
    float4* p = (float4*)(g_h1 + (size_t)d * H) + lane;
    float4 cur = *p;
    cur.x += acc.x; cur.y += acc.y; cur.z += acc.z; cur.w += acc.w;
    *p = cur;
}

// ===== tail MLP via MMA: out = relu(relu(h1)@W2 + b2) @ W3 + b3 ==============
__global__ void __launch_bounds__(512, 1) k_mlp_mma(
    const float* __restrict__ W2, const float* __restrict__ b2,
    const float* __restrict__ W3, const float* __restrict__ b3,
    float* __restrict__ out) {
    extern __shared__ char dsraw[];
    __shared__ float s_w3[64], s_b2[64], s_out[256];
    const uint32_t raw  = smem_u32(dsraw);
    const uint32_t base = (raw + 1023u) & ~1023u;
    char* dsm = dsraw + (base - raw);
    const int tid = threadIdx.x, warp = tid >> 5, lane = tid & 31;

    char* Ahp = dsm;
    char* Alp = dsm + ATILE2;
    char* Bhp = dsm + 2 * ATILE2;
    char* Blp = Bhp + W2T;
    for (int i = tid; i < 64 * H; i += 512) {
        const int k = i >> 6, n = i & 63;
        const float w = W2[k * 64 + n];
        const __nv_bfloat16 h = __float2bfloat16(w);
        *(__nv_bfloat16*)(Bhp + n * SA + k * 2) = h;
        *(__nv_bfloat16*)(Blp + n * SA + k * 2) = __float2bfloat16(w - __bfloat162float(h));
    }
    if (tid < 64) { s_w3[tid] = W3[tid]; s_b2[tid] = b2[tid]; }
    const float b3v = __ldg(b3);
    __syncthreads();

    const uint32_t AhA = smem_u32(Ahp), AlA = smem_u32(Alp);
    const uint32_t BhA = smem_u32(Bhp), BlA = smem_u32(Blp);
    const int rbw = (warp & 7) * 32;
    const int ch  = warp >> 3;

    for (int tile = blockIdx.x; tile < NUM_TX / 256; tile += gridDim.x) {
        const int rb = tile * 256;
        if (tid < 256) s_out[tid] = 0.0f;
        {
            const int r = tid >> 1, hf = tid & 1;
            const float4* src = (const float4*)(g_h1 + (size_t)(rb + r) * H) + hf * 16;
            char* ah = Ahp + r * SA + hf * 128;
            char* al = Alp + r * SA + hf * 128;
            #pragma unroll
            for (int j = 0; j < 16; j++) {
                float4 v = __ldg(src + j);
                v.x = fmaxf(v.x, 0.0f); v.y = fmaxf(v.y, 0.0f);
                v.z = fmaxf(v.z, 0.0f); v.w = fmaxf(v.w, 0.0f);
                uint32_t hi[2], lo[2];
                split4(v, hi, lo);
                *(uint32_t*)(ah + j * 8)     = hi[0];
                *(uint32_t*)(ah + j * 8 + 4) = hi[1];
                *(uint32_t*)(al + j * 8)     = lo[0];
                *(uint32_t*)(al + j * 8 + 4) = lo[1];
            }
        }
        __syncthreads();

        float acc[2][4][4];
        #pragma unroll
        for (int mt = 0; mt < 2; mt++)
            #pragma unroll
            for (int nt = 0; nt < 4; nt++)
                #pragma unroll
                for (int q = 0; q < 4; q++) acc[mt][nt][q] = 0.0f;

        {
            const uint32_t arow = rbw + (lane & 15);
            const uint32_t aqof = (lane >> 4) * 16;
            const uint32_t brow = ch * 32 + ((lane >> 4) * 8) + (lane & 7);
            const uint32_t bqof = ((lane >> 3) & 1) * 16;
            #pragma unroll
            for (int ks = 0; ks < 8; ks++) {
                const uint32_t kb = ks * 32;
                uint32_t ah[2][4], al[2][4], bh_[2][4], bl_[2][4];
                #pragma unroll
                for (int mt = 0; mt < 2; mt++) {
                    const uint32_t ao = (arow + mt * 16) * SA + kb + aqof;
                    ldmx4(ah[mt], AhA + ao);
                    ldmx4(al[mt], AlA + ao);
                }
                #pragma unroll
                for (int np = 0; np < 2; np++) {
                    const uint32_t bo = (brow + np * 16) * SA + kb + bqof;
                    ldmx4(bh_[np], BhA + bo);
                    ldmx4(bl_[np], BlA + bo);
                }
                #pragma unroll
                for (int np = 0; np < 2; np++)
                    #pragma unroll
                    for (int sb = 0; sb < 2; sb++) {
                        const int nt = np * 2 + sb;
                        #pragma unroll
                        for (int mt = 0; mt < 2; mt++) {
                            mma_bf16(acc[mt][nt], ah[mt], bh_[np][sb*2], bh_[np][sb*2+1]);
                            mma_bf16(acc[mt][nt], al[mt], bh_[np][sb*2], bh_[np][sb*2+1]);
                            mma_bf16(acc[mt][nt], ah[mt], bl_[np][sb*2], bl_[np][sb*2+1]);
                        }
                    }
            }
        }

        #pragma unroll
        for (int mt = 0; mt < 2; mt++) {
            const int row0 = rbw + mt * 16 + (lane >> 2), row1 = row0 + 8;
            float p0 = 0.0f, p1 = 0.0f;
            #pragma unroll
            for (int nt = 0; nt < 4; nt++) {
                const int col = ch * 32 + nt * 8 + (lane & 3) * 2;
                p0 += fmaxf(acc[mt][nt][0] + s_b2[col],     0.0f) * s_w3[col]
                    + fmaxf(acc[mt][nt][1] + s_b2[col + 1], 0.0f) * s_w3[col + 1];
                p1 += fmaxf(acc[mt][nt][2] + s_b2[col],     0.0f) * s_w3[col]
                    + fmaxf(acc[mt][nt][3] + s_b2[col + 1], 0.0f) * s_w3[col + 1];
            }
            #pragma unroll
            for (int o = 1; o < 4; o <<= 1) {
                p0 += __shfl_xor_sync(0xffffffffu, p0, o);
                p1 += __shfl_xor_sync(0xffffffffu, p1, o);
            }
            if ((lane & 3) == 0) {
                atomicAdd(&s_out[row0], p0);
                atomicAdd(&s_out[row1], p1);
            }
        }
        __syncthreads();
        if (tid < 256) out[rb + tid] = s_out[tid] + b3v;
        __syncthreads();
    }
}

// ================= host launcher =============================================
extern "C" void kernel_launch(void* const* d_in, const int* in_sizes, int n_in,
                              void* d_out, int out_size) {
    const float* tx_x = (const float*)d_in[0];
    const float* emb  = (const float*)d_in[1];
    const int*   eidx = (const int*)  d_in[2];
    const int*   esrc = (const int*)  d_in[3];
    const int*   edst = (const int*)  d_in[4];
    const float* Wq = (const float*)d_in[5],  *bq = (const float*)d_in[6];
    const float* Wk = (const float*)d_in[7];
    const float* Wv = (const float*)d_in[9],  *bv = (const float*)d_in[10];
    const float* Ws = (const float*)d_in[11], *bs = (const float*)d_in[12];
    const float* lns = (const float*)d_in[13], *lnb = (const float*)d_in[14];
    const float* W1 = (const float*)d_in[15], *b1 = (const float*)d_in[16];
    const float* W2 = (const float*)d_in[17], *b2 = (const float*)d_in[18];
    const float* W3 = (const float*)d_in[19], *b3 = (const float*)d_in[20];
    float* out = (float*)d_out;

    const int SM256    = 2 * ATILE2 + 2 * BTILE + 1024;  // 209920
    const int MLP_SMEM = 2 * ATILE2 + 2 * W2T + 1024;    // 175104
    cudaFuncSetAttribute(k_init_mma, cudaFuncAttributeMaxDynamicSharedMemorySize, SM256);
    cudaFuncSetAttribute(k_z_mma,    cudaFuncAttributeMaxDynamicSharedMemorySize, SM256);
    cudaFuncSetAttribute(k_fused,    cudaFuncAttributeMaxDynamicSharedMemorySize, SM256);
    cudaFuncSetAttribute(k_mlp_mma,  cudaFuncAttributeMaxDynamicSharedMemorySize, MLP_SMEM);

    k_prep <<<128, 128>>>(Wq, Wk, bq);
    k_mkimg<<<2 + T_TYPES, 256>>>(Wv, Ws, W1);

    k_zero_deg<<<(T_TYPES * N_ENT + 255) / 256, 256>>>();
    k_count   <<<(T_TYPES * NE + 255) / 256, 256>>>(edst);
    k_scanA   <<<T_TYPES * 64, 256>>>();
    k_scanB   <<<T_TYPES, 64>>>();
    k_scanC   <<<T_TYPES * 64, 256>>>();
    k_fill    <<<(T_TYPES * NE + 255) / 256, 256>>>(esrc, edst);

    k_init_mma<<<148, 512, SM256>>>(tx_x, W1, b1);

    k_z_mma  <<<148, 512, SM256>>>(emb, eidx);
    k_attn   <<<T_TYPES * (N_ENT / 8), 256>>>();
    k_fused  <<<148, 512, SM256>>>(bv, bs, lns, lnb);
    k_h1add_all<<<NUM_TX / 8, 256>>>();

    k_mlp_mma<<<148, 512, MLP_SMEM>>>(W2, b2, W3, b3, out);
}